// round 4
// baseline (speedup 1.0000x reference)
#include <cuda_runtime.h>
#include <cstdint>

// Problem constants
// B=16, H=W=56, C=512, WS=7, NH=16, HD=32, HID=2048, N=49, NW=64
// M = B*H*W = 50176 rows; window rows = (B*NW)*49 = 50176 as well.

#define M_ROWS 50176
#define C_DIM  512
#define HID_DIM 2048
#define SCALE_ATTN 0.17677669529663687f  // 32^-0.5
#define INV_SQRT2  0.70710678118654752f

// ---------------- scratch (static device allocations; no cudaMalloc) -------
__device__ float g_h[50176 * 512];        // LN1 out (window order) / LN2 out (row order)
__device__ float g_q[50176 * 512];        // window order; attention writes its output back here
__device__ float g_k[50176 * 512];
__device__ float g_v[50176 * 512];
__device__ float g_hidden[102760448];     // 50176 * 2048

// ---------------- small helpers -------------------------------------------
__device__ __forceinline__ unsigned f2tf(float f) {
    unsigned u;
    asm("cvt.rna.tf32.f32 %0, %1;" : "=r"(u) : "f"(f));
    return u;
}

__device__ __forceinline__ void mma8(float c[4],
                                     unsigned a0, unsigned a1, unsigned a2, unsigned a3,
                                     unsigned b0, unsigned b1) {
    asm volatile(
        "mma.sync.aligned.m16n8k8.row.col.f32.tf32.tf32.f32 "
        "{%0,%1,%2,%3},{%4,%5,%6,%7},{%8,%9},{%0,%1,%2,%3};"
        : "+f"(c[0]), "+f"(c[1]), "+f"(c[2]), "+f"(c[3])
        : "r"(a0), "r"(a1), "r"(a2), "r"(a3), "r"(b0), "r"(b1));
}

// (b,l) row -> window-partitioned row
__device__ __forceinline__ int map_fwd(int r) {
    int b = r / 3136; int l = r - b * 3136;
    int hh = l / 56;  int ww = l - hh * 56;
    int win = (hh / 7) * 8 + (ww / 7);
    int n   = (hh % 7) * 7 + (ww % 7);
    return (b * 64 + win) * 49 + n;
}

// window-partitioned row -> (b,l) row
__device__ __forceinline__ int map_inv(int wr) {
    int winG = wr / 49; int n = wr - winG * 49;
    int b = winG >> 6;  int w = winG & 63;
    int hh = (w >> 3) * 7 + n / 7;
    int ww = (w & 7) * 7 + (n % 7);
    return b * 3136 + hh * 56 + ww;
}

// ---------------- LayerNorm (one block per row of 512) --------------------
template<bool PERM>
__global__ __launch_bounds__(128) void ln_kernel(const float* __restrict__ in,
                                                 const float* __restrict__ gamma,
                                                 const float* __restrict__ beta) {
    int row = blockIdx.x;
    int tid = threadIdx.x;
    const float4 v = *((const float4*)(in + (size_t)row * 512) + tid);
    float s = v.x + v.y + v.z + v.w;
    float q = v.x * v.x + v.y * v.y + v.z * v.z + v.w * v.w;
#pragma unroll
    for (int o = 16; o > 0; o >>= 1) {
        s += __shfl_xor_sync(0xffffffffu, s, o);
        q += __shfl_xor_sync(0xffffffffu, q, o);
    }
    __shared__ float red[8];
    int wid = tid >> 5;
    if ((tid & 31) == 0) { red[wid] = s; red[4 + wid] = q; }
    __syncthreads();
    s = red[0] + red[1] + red[2] + red[3];
    q = red[4] + red[5] + red[6] + red[7];
    float mu   = s * (1.0f / 512.0f);
    float var  = q * (1.0f / 512.0f) - mu * mu;
    float rstd = rsqrtf(var + 1e-5f);
    float4 g = *((const float4*)gamma + tid);
    float4 b = *((const float4*)beta + tid);
    float4 o;
    o.x = (v.x - mu) * rstd * g.x + b.x;
    o.y = (v.y - mu) * rstd * g.y + b.y;
    o.z = (v.z - mu) * rstd * g.z + b.z;
    o.w = (v.w - mu) * rstd * g.w + b.w;
    int orow = PERM ? map_fwd(row) : row;
    *((float4*)(g_h + (size_t)orow * 512) + tid) = o;
}

// ---------------- tf32 tensor-core GEMM body -------------------------------
// C[M x N] = A[M x K] @ W[K x N] + bias, tile 128x64x32, 256 threads (8 warps 4x2).
// EPI: 0=store  1=GELU  2=window-reverse + residual(x)->dout  3=dout += val
template<int EPI>
__device__ __forceinline__ void gemm_body(const float* __restrict__ A,
                                          const float* __restrict__ W,
                                          const float* __restrict__ bias,
                                          float* __restrict__ C,
                                          const float* __restrict__ xres,
                                          float* __restrict__ dout,
                                          int N, int K, int rowBase, int colBase) {
    __shared__ unsigned As[128][36];   // pitch 36 (=4 mod 32): conflict-free frag loads
    __shared__ unsigned Bs[32][72];    // pitch 72 (=8 mod 32)
    int tid  = threadIdx.x;
    int lane = tid & 31, wid = tid >> 5;
    int gid = lane >> 2, tig = lane & 3;
    int wm = wid & 3, wn = wid >> 2;

    float acc[2][4][4];
#pragma unroll
    for (int a = 0; a < 2; a++)
#pragma unroll
        for (int b = 0; b < 4; b++)
#pragma unroll
            for (int c = 0; c < 4; c++) acc[a][b][c] = 0.f;

    int ra = tid >> 3, kc = (tid & 7) * 4;    // A stage: 32 rows/pass, 8 thr/row
    int kb = tid >> 4, nc = (tid & 15) * 4;   // B stage: 16 k/pass, 16 thr/k

    for (int k0 = 0; k0 < K; k0 += 32) {
#pragma unroll
        for (int p = 0; p < 4; p++) {
            int r = ra + p * 32;
            float4 v = *(const float4*)(A + (size_t)(rowBase + r) * K + k0 + kc);
            As[r][kc + 0] = f2tf(v.x); As[r][kc + 1] = f2tf(v.y);
            As[r][kc + 2] = f2tf(v.z); As[r][kc + 3] = f2tf(v.w);
        }
#pragma unroll
        for (int p = 0; p < 2; p++) {
            int kk = kb + p * 16;
            float4 v = *(const float4*)(W + (size_t)(k0 + kk) * N + colBase + nc);
            Bs[kk][nc + 0] = f2tf(v.x); Bs[kk][nc + 1] = f2tf(v.y);
            Bs[kk][nc + 2] = f2tf(v.z); Bs[kk][nc + 3] = f2tf(v.w);
        }
        __syncthreads();
#pragma unroll
        for (int kt = 0; kt < 4; kt++) {
            int k8 = kt * 8;
            unsigned a[2][4];
#pragma unroll
            for (int mt = 0; mt < 2; mt++) {
                int r0 = wm * 32 + mt * 16 + gid;
                a[mt][0] = As[r0][k8 + tig];
                a[mt][1] = As[r0 + 8][k8 + tig];
                a[mt][2] = As[r0][k8 + tig + 4];
                a[mt][3] = As[r0 + 8][k8 + tig + 4];
            }
#pragma unroll
            for (int nt = 0; nt < 4; nt++) {
                int cb = wn * 32 + nt * 8 + gid;
                unsigned b0 = Bs[k8 + tig][cb];
                unsigned b1 = Bs[k8 + tig + 4][cb];
                mma8(acc[0][nt], a[0][0], a[0][1], a[0][2], a[0][3], b0, b1);
                mma8(acc[1][nt], a[1][0], a[1][1], a[1][2], a[1][3], b0, b1);
            }
        }
        __syncthreads();
    }

#pragma unroll
    for (int mt = 0; mt < 2; mt++) {
#pragma unroll
        for (int nt = 0; nt < 4; nt++) {
            int col = colBase + wn * 32 + nt * 8 + tig * 2;
            float b0v = bias[col], b1v = bias[col + 1];
#pragma unroll
            for (int h = 0; h < 2; h++) {
                int row = rowBase + wm * 32 + mt * 16 + gid + h * 8;
                float v0 = acc[mt][nt][h * 2 + 0] + b0v;
                float v1 = acc[mt][nt][h * 2 + 1] + b1v;
                if (EPI == 0) {
                    *(float2*)(C + (size_t)row * N + col) = make_float2(v0, v1);
                } else if (EPI == 1) {
                    float g0 = 0.5f * v0 * (1.0f + erff(v0 * INV_SQRT2));
                    float g1 = 0.5f * v1 * (1.0f + erff(v1 * INV_SQRT2));
                    *(float2*)(C + (size_t)row * N + col) = make_float2(g0, g1);
                } else if (EPI == 2) {
                    int r = map_inv(row);
                    size_t o = (size_t)r * 512 + col;
                    dout[o]     = xres[o]     + v0;
                    dout[o + 1] = xres[o + 1] + v1;
                } else {
                    size_t o = (size_t)row * N + col;
                    dout[o]     += v0;
                    dout[o + 1] += v1;
                }
            }
        }
    }
}

// ---------------- GEMM kernel wrappers -------------------------------------
__global__ __launch_bounds__(256) void k_gemm_qkv(const float* __restrict__ Wq,
                                                  const float* __restrict__ Wk,
                                                  const float* __restrict__ Wv,
                                                  const float* __restrict__ bq,
                                                  const float* __restrict__ bk,
                                                  const float* __restrict__ bv) {
    int sel = blockIdx.x >> 3;
    const float* W    = (sel == 0) ? Wq : ((sel == 1) ? Wk : Wv);
    const float* bias = (sel == 0) ? bq : ((sel == 1) ? bk : bv);
    float* C          = (sel == 0) ? g_q : ((sel == 1) ? g_k : g_v);
    gemm_body<0>(g_h, W, bias, C, nullptr, nullptr, 512, 512,
                 blockIdx.y * 128, (blockIdx.x & 7) * 64);
}

__global__ __launch_bounds__(256) void k_gemm_proj(const float* __restrict__ Wp,
                                                   const float* __restrict__ bp,
                                                   const float* __restrict__ x,
                                                   float* __restrict__ dout) {
    // A = attention output (stored in-place in g_q, window order)
    gemm_body<2>(g_q, Wp, bp, nullptr, x, dout, 512, 512,
                 blockIdx.y * 128, blockIdx.x * 64);
}

__global__ __launch_bounds__(256) void k_gemm_mlp1(const float* __restrict__ W1,
                                                   const float* __restrict__ b1) {
    gemm_body<1>(g_h, W1, b1, g_hidden, nullptr, nullptr, 2048, 512,
                 blockIdx.y * 128, blockIdx.x * 64);
}

__global__ __launch_bounds__(256) void k_gemm_mlp2(const float* __restrict__ W2,
                                                   const float* __restrict__ b2,
                                                   float* __restrict__ dout) {
    gemm_body<3>(g_hidden, W2, b2, nullptr, nullptr, dout, 512, 2048,
                 blockIdx.y * 128, blockIdx.x * 64);
}

// ---------------- fused window attention -----------------------------------
// One block per (window, head): S = (Q*scale)K^T + bias, softmax, O = P V.
// Padded M: 49->64 rows, N(keys): 49->56. mma.sync m16n8k8 tf32.
// Output written back IN PLACE into g_q (block reads all its Q into smem first;
// blocks partition [row, col] space disjointly, so this is race-free).
__global__ __launch_bounds__(128) void k_attn(const float* __restrict__ relb) {
    __shared__ unsigned qs[64][36];
    __shared__ unsigned ks[56][36];
    __shared__ unsigned vs[56][40];
    __shared__ float    sm[64][60];
    int win = blockIdx.x, head = blockIdx.y;
    int tid = threadIdx.x;
    int wid = tid >> 5, lane = tid & 31;
    int gid = lane >> 2, tig = lane & 3;
    size_t base = ((size_t)win * 49) * 512 + head * 32;

    for (int i = tid; i < 64 * 32; i += 128) {
        int r = i >> 5, d = i & 31;
        float v = (r < 49) ? g_q[base + (size_t)r * 512 + d] * SCALE_ATTN : 0.f;
        qs[r][d] = f2tf(v);
    }
    for (int i = tid; i < 56 * 32; i += 128) {
        int r = i >> 5, d = i & 31;
        float kv = (r < 49) ? g_k[base + (size_t)r * 512 + d] : 0.f;
        ks[r][d] = f2tf(kv);
        float vv = (r < 49) ? g_v[base + (size_t)r * 512 + d] : 0.f;
        vs[r][d] = f2tf(vv);
    }
    __syncthreads();

    int wr = wid * 16;  // each warp owns 16 query rows
    {   // S = Q K^T : warp tile 16x56, K=32
        float acc[7][4];
#pragma unroll
        for (int nt = 0; nt < 7; nt++)
#pragma unroll
            for (int e = 0; e < 4; e++) acc[nt][e] = 0.f;
#pragma unroll
        for (int kt = 0; kt < 4; kt++) {
            int k8 = kt * 8;
            unsigned a0 = qs[wr + gid][k8 + tig];
            unsigned a1 = qs[wr + gid + 8][k8 + tig];
            unsigned a2 = qs[wr + gid][k8 + tig + 4];
            unsigned a3 = qs[wr + gid + 8][k8 + tig + 4];
#pragma unroll
            for (int nt = 0; nt < 7; nt++) {
                unsigned b0 = ks[nt * 8 + gid][k8 + tig];
                unsigned b1 = ks[nt * 8 + gid][k8 + tig + 4];
                mma8(acc[nt], a0, a1, a2, a3, b0, b1);
            }
        }
        const float* bh = relb + head * 2401;
#pragma unroll
        for (int nt = 0; nt < 7; nt++)
#pragma unroll
            for (int e = 0; e < 4; e++) {
                int i = wr + gid + (e >> 1) * 8;
                int j = nt * 8 + tig * 2 + (e & 1);
                float v = acc[nt][e];
                if (j < 49) { if (i < 49) v += bh[i * 49 + j]; }
                else v = -1e30f;
                sm[i][j] = v;
            }
    }
    __syncwarp();
    // softmax over 56 cols (cols>=49 hold -1e30 -> exp 0)
    for (int i = wr; i < wr + 16; i++) {
        float x0 = sm[i][lane];
        float x1 = (lane < 24) ? sm[i][lane + 32] : -1e30f;
        float m = fmaxf(x0, x1);
#pragma unroll
        for (int o = 16; o > 0; o >>= 1) m = fmaxf(m, __shfl_xor_sync(0xffffffffu, m, o));
        float e0 = expf(x0 - m);
        float e1 = (lane < 24) ? expf(x1 - m) : 0.f;
        float s = e0 + e1;
#pragma unroll
        for (int o = 16; o > 0; o >>= 1) s += __shfl_xor_sync(0xffffffffu, s, o);
        float inv = 1.0f / s;
        sm[i][lane] = e0 * inv;
        if (lane < 24) sm[i][lane + 32] = e1 * inv;
    }
    __syncwarp();
    {   // O = P V : warp tile 16x32, K=56
        float acc[4][4];
#pragma unroll
        for (int nt = 0; nt < 4; nt++)
#pragma unroll
            for (int e = 0; e < 4; e++) acc[nt][e] = 0.f;
#pragma unroll
        for (int jt = 0; jt < 7; jt++) {
            int j8 = jt * 8;
            unsigned a0 = f2tf(sm[wr + gid][j8 + tig]);
            unsigned a1 = f2tf(sm[wr + gid + 8][j8 + tig]);
            unsigned a2 = f2tf(sm[wr + gid][j8 + tig + 4]);
            unsigned a3 = f2tf(sm[wr + gid + 8][j8 + tig + 4]);
#pragma unroll
            for (int nt = 0; nt < 4; nt++) {
                unsigned b0 = vs[j8 + tig][nt * 8 + gid];
                unsigned b1 = vs[j8 + tig + 4][nt * 8 + gid];
                mma8(acc[nt], a0, a1, a2, a3, b0, b1);
            }
        }
#pragma unroll
        for (int nt = 0; nt < 4; nt++)
#pragma unroll
            for (int e = 0; e < 4; e++) {
                int i = wr + gid + (e >> 1) * 8;
                int d = nt * 8 + tig * 2 + (e & 1);
                if (i < 49) g_q[base + (size_t)i * 512 + d] = acc[nt][e];
            }
    }
}

// ---------------- launch ----------------------------------------------------
extern "C" void kernel_launch(void* const* d_in, const int* in_sizes, int n_in,
                              void* d_out, int out_size) {
    const float* x   = (const float*)d_in[0];
    const float* Wq  = (const float*)d_in[1];
    const float* bq  = (const float*)d_in[2];
    const float* Wk  = (const float*)d_in[3];
    const float* bk  = (const float*)d_in[4];
    const float* Wv  = (const float*)d_in[5];
    const float* bv  = (const float*)d_in[6];
    const float* Wp  = (const float*)d_in[7];
    const float* bp  = (const float*)d_in[8];
    const float* rb  = (const float*)d_in[9];
    const float* g1  = (const float*)d_in[10];
    const float* b1  = (const float*)d_in[11];
    const float* g2  = (const float*)d_in[12];
    const float* b2  = (const float*)d_in[13];
    const float* W1  = (const float*)d_in[14];
    const float* bf1 = (const float*)d_in[15];
    const float* W2  = (const float*)d_in[16];
    const float* bf2 = (const float*)d_in[17];
    float* out = (float*)d_out;

    // 1. LN1 + window partition permute -> g_h (window order)
    ln_kernel<true><<<M_ROWS, 128>>>(x, g1, b1);
    // 2. fused Q/K/V projection (one launch, 3 weight panels)
    k_gemm_qkv<<<dim3(24, 392), 256>>>(Wq, Wk, Wv, bq, bk, bv);
    // 3. windowed attention (output in place into g_q)
    k_attn<<<dim3(1024, 16), 128>>>(rb);
    // 4. output projection + window reverse + residual -> d_out (= y)
    k_gemm_proj<<<dim3(8, 392), 256>>>(Wp, bp, x, out);
    // 5. LN2 -> g_h (row order)
    ln_kernel<false><<<M_ROWS, 128>>>(out, g2, b2);
    // 6. MLP fc1 + exact GELU -> g_hidden
    k_gemm_mlp1<<<dim3(32, 392), 256>>>(W1, bf1);
    // 7. MLP fc2 + residual add into d_out
    k_gemm_mlp2<<<dim3(8, 392), 256>>>(W2, bf2, out);
}

// round 6
// speedup vs baseline: 1.8392x; 1.8392x over previous
#include <cuda_runtime.h>
#include <cstdint>

// Problem constants
// B=16, H=W=56, C=512, WS=7, NH=16, HD=32, HID=2048, N=49, NW=64
#define M_ROWS 50176
#define SCALE_ATTN 0.17677669529663687f  // 32^-0.5
#define INV_SQRT2  0.70710678118654752f

// GEMM tiling
#define A_PITCH 36            // 128 x 32 A tile, pitch 36 (4 mod 32)
#define B_PITCH 136           // 32 x 128 B tile, pitch 136 (8 mod 32)
#define A_STG (128 * A_PITCH) // 4608 words
#define B_STG (32 * B_PITCH)  // 4352 words
#define SMEM_WORDS (2 * A_STG + 2 * B_STG)
#define SMEM_BYTES (SMEM_WORDS * 4)   // 71680

// ---------------- scratch (static device allocations; no cudaMalloc) -------
__device__ float g_h[50176 * 512];        // LN1 out (window order) / LN2 out (row order)
__device__ float g_q[50176 * 512];        // window order; attention output in place
__device__ float g_k[50176 * 512];
__device__ float g_v[50176 * 512];
__device__ float g_hidden[102760448];     // 50176 * 2048

// ---------------- small helpers -------------------------------------------
__device__ __forceinline__ unsigned f2tf(float f) {
    unsigned u;
    asm("cvt.rna.tf32.f32 %0, %1;" : "=r"(u) : "f"(f));
    return u;
}

__device__ __forceinline__ void mma8(float c[4],
                                     unsigned a0, unsigned a1, unsigned a2, unsigned a3,
                                     unsigned b0, unsigned b1) {
    asm volatile(
        "mma.sync.aligned.m16n8k8.row.col.f32.tf32.tf32.f32 "
        "{%0,%1,%2,%3},{%4,%5,%6,%7},{%8,%9},{%0,%1,%2,%3};"
        : "+f"(c[0]), "+f"(c[1]), "+f"(c[2]), "+f"(c[3])
        : "r"(a0), "r"(a1), "r"(a2), "r"(a3), "r"(b0), "r"(b1));
}

__device__ __forceinline__ void cpa16(uint32_t dst, const float* src) {
    asm volatile("cp.async.cg.shared.global [%0], [%1], 16;" :: "r"(dst), "l"(src));
}
__device__ __forceinline__ void cpa_commit() {
    asm volatile("cp.async.commit_group;");
}
template<int N>
__device__ __forceinline__ void cpa_wait() {
    asm volatile("cp.async.wait_group %0;" :: "n"(N));
}

// (b,l) row -> window-partitioned row
__device__ __forceinline__ int map_fwd(int r) {
    int b = r / 3136; int l = r - b * 3136;
    int hh = l / 56;  int ww = l - hh * 56;
    int win = (hh / 7) * 8 + (ww / 7);
    int n   = (hh % 7) * 7 + (ww % 7);
    return (b * 64 + win) * 49 + n;
}

// window-partitioned row -> (b,l) row
__device__ __forceinline__ int map_inv(int wr) {
    int winG = wr / 49; int n = wr - winG * 49;
    int b = winG >> 6;  int w = winG & 63;
    int hh = (w >> 3) * 7 + n / 7;
    int ww = (w & 7) * 7 + (n % 7);
    return b * 3136 + hh * 56 + ww;
}

// ---------------- LayerNorm (one block per row of 512) --------------------
template<bool PERM>
__global__ __launch_bounds__(128) void ln_kernel(const float* __restrict__ in,
                                                 const float* __restrict__ gamma,
                                                 const float* __restrict__ beta) {
    int row = blockIdx.x;
    int tid = threadIdx.x;
    const float4 v = *((const float4*)(in + (size_t)row * 512) + tid);
    float s = v.x + v.y + v.z + v.w;
    float q = v.x * v.x + v.y * v.y + v.z * v.z + v.w * v.w;
#pragma unroll
    for (int o = 16; o > 0; o >>= 1) {
        s += __shfl_xor_sync(0xffffffffu, s, o);
        q += __shfl_xor_sync(0xffffffffu, q, o);
    }
    __shared__ float red[8];
    int wid = tid >> 5;
    if ((tid & 31) == 0) { red[wid] = s; red[4 + wid] = q; }
    __syncthreads();
    s = red[0] + red[1] + red[2] + red[3];
    q = red[4] + red[5] + red[6] + red[7];
    float mu   = s * (1.0f / 512.0f);
    float var  = q * (1.0f / 512.0f) - mu * mu;
    float rstd = rsqrtf(var + 1e-5f);
    float4 g = *((const float4*)gamma + tid);
    float4 b = *((const float4*)beta + tid);
    float4 o;
    o.x = (v.x - mu) * rstd * g.x + b.x;
    o.y = (v.y - mu) * rstd * g.y + b.y;
    o.z = (v.z - mu) * rstd * g.z + b.z;
    o.w = (v.w - mu) * rstd * g.w + b.w;
    int orow = PERM ? map_fwd(row) : row;
    *((float4*)(g_h + (size_t)orow * 512) + tid) = o;
}

// ---------------- tf32 tensor-core GEMM body -------------------------------
// C[M x N] = A[M x K] @ W[K x N] + bias.
// Block tile 128x128x32, 256 threads = 8 warps (2 m x 4 n), warp tile 64x32.
// Double-buffered smem, cp.async pipeline. A/B fed to mma as raw fp32 bits
// (tf32 truncation in HW).
// EPI: 0=store  1=GELU  2=window-reverse + residual(x)->dout  3=dout += val
template<int EPI>
__device__ __forceinline__ void gemm_body(const float* __restrict__ A,
                                          const float* __restrict__ W,
                                          const float* __restrict__ bias,
                                          float* __restrict__ C,
                                          const float* __restrict__ xres,
                                          float* __restrict__ dout,
                                          int N, int K, int rowBase, int colBase) {
    extern __shared__ float sm[];
    float* AsBase = sm;               // [2][128][A_PITCH]
    float* BsBase = sm + 2 * A_STG;   // [2][32][B_PITCH]

    int tid  = threadIdx.x;
    int lane = tid & 31, wid = tid >> 5;
    int gid = lane >> 2, tig = lane & 3;
    int wm = wid & 1, wn = wid >> 1;

    // loader mapping
    int arow  = tid >> 3;             // 0..31 (+p*32)
    int acol  = (tid & 7) * 4;        // k within 32-chunk
    int brow  = tid >> 3;             // k row 0..31
    int bcol0 = (tid & 7) * 4;        // n within 128 (+p*32)

    const float* Ag = A + (size_t)rowBase * K;
    const float* Wg = W + colBase;

    uint32_t saB = (uint32_t)__cvta_generic_to_shared(AsBase);
    uint32_t sbB = (uint32_t)__cvta_generic_to_shared(BsBase);

    float acc[4][4][4];
#pragma unroll
    for (int a = 0; a < 4; a++)
#pragma unroll
        for (int b = 0; b < 4; b++)
#pragma unroll
            for (int c = 0; c < 4; c++) acc[a][b][c] = 0.f;

    // prefetch stage 0
    {
        uint32_t sa = saB, sb = sbB;
#pragma unroll
        for (int p = 0; p < 4; p++) {
            int r = arow + p * 32;
            cpa16(sa + (uint32_t)(r * A_PITCH + acol) * 4u, Ag + (size_t)r * K + acol);
        }
#pragma unroll
        for (int p = 0; p < 4; p++) {
            int n4 = bcol0 + p * 32;
            cpa16(sb + (uint32_t)(brow * B_PITCH + n4) * 4u, Wg + (size_t)brow * N + n4);
        }
        cpa_commit();
    }

    for (int k0 = 0; k0 < K; k0 += 32) {
        int buf = (k0 >> 5) & 1;
        if (k0 + 32 < K) {
            int nb = buf ^ 1;
            uint32_t sa = saB + (uint32_t)(nb * A_STG) * 4u;
            uint32_t sb = sbB + (uint32_t)(nb * B_STG) * 4u;
            int kn = k0 + 32;
#pragma unroll
            for (int p = 0; p < 4; p++) {
                int r = arow + p * 32;
                cpa16(sa + (uint32_t)(r * A_PITCH + acol) * 4u, Ag + (size_t)r * K + kn + acol);
            }
#pragma unroll
            for (int p = 0; p < 4; p++) {
                int n4 = bcol0 + p * 32;
                cpa16(sb + (uint32_t)(brow * B_PITCH + n4) * 4u, Wg + (size_t)(kn + brow) * N + n4);
            }
            cpa_commit();
            cpa_wait<1>();
        } else {
            cpa_wait<0>();
        }
        __syncthreads();

        const float* Ab = AsBase + buf * A_STG;
        const float* Bb = BsBase + buf * B_STG;
#pragma unroll
        for (int kt = 0; kt < 4; kt++) {
            int k8 = kt * 8;
            unsigned a[4][4];
#pragma unroll
            for (int mt = 0; mt < 4; mt++) {
                int r0 = wm * 64 + mt * 16 + gid;
                a[mt][0] = __float_as_uint(Ab[r0 * A_PITCH + k8 + tig]);
                a[mt][1] = __float_as_uint(Ab[(r0 + 8) * A_PITCH + k8 + tig]);
                a[mt][2] = __float_as_uint(Ab[r0 * A_PITCH + k8 + tig + 4]);
                a[mt][3] = __float_as_uint(Ab[(r0 + 8) * A_PITCH + k8 + tig + 4]);
            }
#pragma unroll
            for (int nt = 0; nt < 4; nt++) {
                int cb = wn * 32 + nt * 8 + gid;
                unsigned b0 = __float_as_uint(Bb[(k8 + tig) * B_PITCH + cb]);
                unsigned b1 = __float_as_uint(Bb[(k8 + tig + 4) * B_PITCH + cb]);
#pragma unroll
                for (int mt = 0; mt < 4; mt++)
                    mma8(acc[mt][nt], a[mt][0], a[mt][1], a[mt][2], a[mt][3], b0, b1);
            }
        }
        __syncthreads();
    }

    // epilogue
#pragma unroll
    for (int mt = 0; mt < 4; mt++) {
#pragma unroll
        for (int nt = 0; nt < 4; nt++) {
            int col = colBase + wn * 32 + nt * 8 + tig * 2;
            float b0v = bias[col], b1v = bias[col + 1];
#pragma unroll
            for (int h = 0; h < 2; h++) {
                int row = rowBase + wm * 64 + mt * 16 + gid + h * 8;
                float v0 = acc[mt][nt][h * 2 + 0] + b0v;
                float v1 = acc[mt][nt][h * 2 + 1] + b1v;
                if (EPI == 0) {
                    *(float2*)(C + (size_t)row * N + col) = make_float2(v0, v1);
                } else if (EPI == 1) {
                    float g0 = 0.5f * v0 * (1.0f + erff(v0 * INV_SQRT2));
                    float g1 = 0.5f * v1 * (1.0f + erff(v1 * INV_SQRT2));
                    *(float2*)(C + (size_t)row * N + col) = make_float2(g0, g1);
                } else if (EPI == 2) {
                    int r = map_inv(row);
                    size_t o = (size_t)r * 512 + col;
                    dout[o]     = xres[o]     + v0;
                    dout[o + 1] = xres[o + 1] + v1;
                } else {
                    size_t o = (size_t)row * N + col;
                    dout[o]     += v0;
                    dout[o + 1] += v1;
                }
            }
        }
    }
}

// ---------------- GEMM kernel wrappers -------------------------------------
__global__ __launch_bounds__(256) void k_gemm_qkv(const float* __restrict__ Wq,
                                                  const float* __restrict__ Wk,
                                                  const float* __restrict__ Wv,
                                                  const float* __restrict__ bq,
                                                  const float* __restrict__ bk,
                                                  const float* __restrict__ bv) {
    int sel = blockIdx.x >> 2;
    const float* W    = (sel == 0) ? Wq : ((sel == 1) ? Wk : Wv);
    const float* bias = (sel == 0) ? bq : ((sel == 1) ? bk : bv);
    float* C          = (sel == 0) ? g_q : ((sel == 1) ? g_k : g_v);
    gemm_body<0>(g_h, W, bias, C, nullptr, nullptr, 512, 512,
                 blockIdx.y * 128, (blockIdx.x & 3) * 128);
}

__global__ __launch_bounds__(256) void k_gemm_proj(const float* __restrict__ Wp,
                                                   const float* __restrict__ bp,
                                                   const float* __restrict__ x,
                                                   float* __restrict__ dout) {
    gemm_body<2>(g_q, Wp, bp, nullptr, x, dout, 512, 512,
                 blockIdx.y * 128, blockIdx.x * 128);
}

__global__ __launch_bounds__(256) void k_gemm_mlp1(const float* __restrict__ W1,
                                                   const float* __restrict__ b1) {
    gemm_body<1>(g_h, W1, b1, g_hidden, nullptr, nullptr, 2048, 512,
                 blockIdx.y * 128, blockIdx.x * 128);
}

__global__ __launch_bounds__(256) void k_gemm_mlp2(const float* __restrict__ W2,
                                                   const float* __restrict__ b2,
                                                   float* __restrict__ dout) {
    gemm_body<3>(g_hidden, W2, b2, nullptr, nullptr, dout, 512, 2048,
                 blockIdx.y * 128, blockIdx.x * 128);
}

// ---------------- fused window attention -----------------------------------
// One block per (window, head). Output written in place into g_q.
__global__ __launch_bounds__(128) void k_attn(const float* __restrict__ relb) {
    __shared__ unsigned qs[64][36];
    __shared__ unsigned ks[56][36];
    __shared__ unsigned vs[56][40];
    __shared__ float    smx[64][60];
    int win = blockIdx.x, head = blockIdx.y;
    int tid = threadIdx.x;
    int wid = tid >> 5, lane = tid & 31;
    int gid = lane >> 2, tig = lane & 3;
    size_t base = ((size_t)win * 49) * 512 + head * 32;

    for (int i = tid; i < 64 * 32; i += 128) {
        int r = i >> 5, d = i & 31;
        float v = (r < 49) ? g_q[base + (size_t)r * 512 + d] * SCALE_ATTN : 0.f;
        qs[r][d] = f2tf(v);
    }
    for (int i = tid; i < 56 * 32; i += 128) {
        int r = i >> 5, d = i & 31;
        float kv = (r < 49) ? g_k[base + (size_t)r * 512 + d] : 0.f;
        ks[r][d] = f2tf(kv);
        float vv = (r < 49) ? g_v[base + (size_t)r * 512 + d] : 0.f;
        vs[r][d] = f2tf(vv);
    }
    __syncthreads();

    int wr = wid * 16;
    {   // S = Q K^T : warp tile 16x56
        float acc[7][4];
#pragma unroll
        for (int nt = 0; nt < 7; nt++)
#pragma unroll
            for (int e = 0; e < 4; e++) acc[nt][e] = 0.f;
#pragma unroll
        for (int kt = 0; kt < 4; kt++) {
            int k8 = kt * 8;
            unsigned a0 = qs[wr + gid][k8 + tig];
            unsigned a1 = qs[wr + gid + 8][k8 + tig];
            unsigned a2 = qs[wr + gid][k8 + tig + 4];
            unsigned a3 = qs[wr + gid + 8][k8 + tig + 4];
#pragma unroll
            for (int nt = 0; nt < 7; nt++) {
                unsigned b0 = ks[nt * 8 + gid][k8 + tig];
                unsigned b1 = ks[nt * 8 + gid][k8 + tig + 4];
                mma8(acc[nt], a0, a1, a2, a3, b0, b1);
            }
        }
        const float* bh = relb + head * 2401;
#pragma unroll
        for (int nt = 0; nt < 7; nt++)
#pragma unroll
            for (int e = 0; e < 4; e++) {
                int i = wr + gid + (e >> 1) * 8;
                int j = nt * 8 + tig * 2 + (e & 1);
                float v = acc[nt][e];
                if (j < 49) { if (i < 49) v += bh[i * 49 + j]; }
                else v = -1e30f;
                smx[i][j] = v;
            }
    }
    __syncwarp();
    for (int i = wr; i < wr + 16; i++) {
        float x0 = smx[i][lane];
        float x1 = (lane < 24) ? smx[i][lane + 32] : -1e30f;
        float m = fmaxf(x0, x1);
#pragma unroll
        for (int o = 16; o > 0; o >>= 1) m = fmaxf(m, __shfl_xor_sync(0xffffffffu, m, o));
        float e0 = expf(x0 - m);
        float e1 = (lane < 24) ? expf(x1 - m) : 0.f;
        float s = e0 + e1;
#pragma unroll
        for (int o = 16; o > 0; o >>= 1) s += __shfl_xor_sync(0xffffffffu, s, o);
        float inv = 1.0f / s;
        smx[i][lane] = e0 * inv;
        if (lane < 24) smx[i][lane + 32] = e1 * inv;
    }
    __syncwarp();
    {   // O = P V
        float acc[4][4];
#pragma unroll
        for (int nt = 0; nt < 4; nt++)
#pragma unroll
            for (int e = 0; e < 4; e++) acc[nt][e] = 0.f;
#pragma unroll
        for (int jt = 0; jt < 7; jt++) {
            int j8 = jt * 8;
            unsigned a0 = f2tf(smx[wr + gid][j8 + tig]);
            unsigned a1 = f2tf(smx[wr + gid + 8][j8 + tig]);
            unsigned a2 = f2tf(smx[wr + gid][j8 + tig + 4]);
            unsigned a3 = f2tf(smx[wr + gid + 8][j8 + tig + 4]);
#pragma unroll
            for (int nt = 0; nt < 4; nt++) {
                unsigned b0 = vs[j8 + tig][nt * 8 + gid];
                unsigned b1 = vs[j8 + tig + 4][nt * 8 + gid];
                mma8(acc[nt], a0, a1, a2, a3, b0, b1);
            }
        }
#pragma unroll
        for (int nt = 0; nt < 4; nt++)
#pragma unroll
            for (int e = 0; e < 4; e++) {
                int i = wr + gid + (e >> 1) * 8;
                int d = nt * 8 + tig * 2 + (e & 1);
                if (i < 49) g_q[base + (size_t)i * 512 + d] = acc[nt][e];
            }
    }
}

// ---------------- launch ----------------------------------------------------
extern "C" void kernel_launch(void* const* d_in, const int* in_sizes, int n_in,
                              void* d_out, int out_size) {
    const float* x   = (const float*)d_in[0];
    const float* Wq  = (const float*)d_in[1];
    const float* bq  = (const float*)d_in[2];
    const float* Wk  = (const float*)d_in[3];
    const float* bk  = (const float*)d_in[4];
    const float* Wv  = (const float*)d_in[5];
    const float* bv  = (const float*)d_in[6];
    const float* Wp  = (const float*)d_in[7];
    const float* bp  = (const float*)d_in[8];
    const float* rb  = (const float*)d_in[9];
    const float* g1  = (const float*)d_in[10];
    const float* b1  = (const float*)d_in[11];
    const float* g2  = (const float*)d_in[12];
    const float* b2  = (const float*)d_in[13];
    const float* W1  = (const float*)d_in[14];
    const float* bf1 = (const float*)d_in[15];
    const float* W2  = (const float*)d_in[16];
    const float* bf2 = (const float*)d_in[17];
    float* out = (float*)d_out;

    cudaFuncSetAttribute(k_gemm_qkv,  cudaFuncAttributeMaxDynamicSharedMemorySize, SMEM_BYTES);
    cudaFuncSetAttribute(k_gemm_proj, cudaFuncAttributeMaxDynamicSharedMemorySize, SMEM_BYTES);
    cudaFuncSetAttribute(k_gemm_mlp1, cudaFuncAttributeMaxDynamicSharedMemorySize, SMEM_BYTES);
    cudaFuncSetAttribute(k_gemm_mlp2, cudaFuncAttributeMaxDynamicSharedMemorySize, SMEM_BYTES);

    // 1. LN1 + window partition permute -> g_h (window order)
    ln_kernel<true><<<M_ROWS, 128>>>(x, g1, b1);
    // 2. fused Q/K/V projection
    k_gemm_qkv<<<dim3(12, 392), 256, SMEM_BYTES>>>(Wq, Wk, Wv, bq, bk, bv);
    // 3. windowed attention (output in place into g_q)
    k_attn<<<dim3(1024, 16), 128>>>(rb);
    // 4. output projection + window reverse + residual -> d_out
    k_gemm_proj<<<dim3(4, 392), 256, SMEM_BYTES>>>(Wp, bp, x, out);
    // 5. LN2 -> g_h (row order)
    ln_kernel<false><<<M_ROWS, 128>>>(out, g2, b2);
    // 6. MLP fc1 + exact GELU -> g_hidden
    k_gemm_mlp1<<<dim3(16, 392), 256, SMEM_BYTES>>>(W1, bf1);
    // 7. MLP fc2 + residual add into d_out
    k_gemm_mlp2<<<dim3(4, 392), 256, SMEM_BYTES>>>(W2, bf2, out);
}

// round 11
// speedup vs baseline: 2.2328x; 1.2140x over previous
#include <cuda_runtime.h>
#include <cuda_fp16.h>
#include <cstdint>

// Problem: B=16, H=W=56, C=512, WS=7, NH=16, HD=32, HID=2048, N=49, NW=64
#define M_ROWS 50176
#define SCALE_ATTN 0.17677669529663687f  // 32^-0.5
#define INV_SQRT2  0.70710678118654752f

// fp16 GEMM: block 128x128x64, 2-stage cp.async. Stage = A 16KB + B 16KB.
#define SMEM_BYTES 65536

// ---------------- scratch (static device allocations) ----------------------
__device__ __half g_hh[50176 * 512];      // LN1 out (window order) / LN2 out (rows)
__device__ __half g_qh[50176 * 512];
__device__ __half g_kh[50176 * 512];
__device__ __half g_vh[50176 * 512];
__device__ __half g_oh[50176 * 512];      // attention output
__device__ __half g_hid[50176 * 2048];
__device__ __half g_wqt[262144], g_wkt[262144], g_wvt[262144], g_wpt[262144];
__device__ __half g_w1t[1048576];         // [2048][512]
__device__ __half g_w2t[1048576];         // [512][2048]

// ---------------- helpers ---------------------------------------------------
__device__ __forceinline__ unsigned f2tf(float f) {
    unsigned u;
    asm("cvt.rna.tf32.f32 %0, %1;" : "=r"(u) : "f"(f));
    return u;
}

__device__ __forceinline__ void mma8(float c[4],
                                     unsigned a0, unsigned a1, unsigned a2, unsigned a3,
                                     unsigned b0, unsigned b1) {
    asm volatile(
        "mma.sync.aligned.m16n8k8.row.col.f32.tf32.tf32.f32 "
        "{%0,%1,%2,%3},{%4,%5,%6,%7},{%8,%9},{%0,%1,%2,%3};"
        : "+f"(c[0]), "+f"(c[1]), "+f"(c[2]), "+f"(c[3])
        : "r"(a0), "r"(a1), "r"(a2), "r"(a3), "r"(b0), "r"(b1));
}

__device__ __forceinline__ void mma16(float c[4], const unsigned a[4],
                                      unsigned b0, unsigned b1) {
    asm volatile(
        "mma.sync.aligned.m16n8k16.row.col.f32.f16.f16.f32 "
        "{%0,%1,%2,%3},{%4,%5,%6,%7},{%8,%9},{%0,%1,%2,%3};"
        : "+f"(c[0]), "+f"(c[1]), "+f"(c[2]), "+f"(c[3])
        : "r"(a[0]), "r"(a[1]), "r"(a[2]), "r"(a[3]), "r"(b0), "r"(b1));
}

__device__ __forceinline__ void ldsm4(unsigned r[4], uint32_t addr) {
    asm volatile("ldmatrix.sync.aligned.m8n8.x4.shared.b16 {%0,%1,%2,%3}, [%4];"
                 : "=r"(r[0]), "=r"(r[1]), "=r"(r[2]), "=r"(r[3]) : "r"(addr));
}

__device__ __forceinline__ void cpa16(uint32_t dst, const void* src) {
    asm volatile("cp.async.cg.shared.global [%0], [%1], 16;" :: "r"(dst), "l"(src));
}
__device__ __forceinline__ void cpa_commit() { asm volatile("cp.async.commit_group;"); }
template<int N>
__device__ __forceinline__ void cpa_wait() { asm volatile("cp.async.wait_group %0;" :: "n"(N)); }

// (b,l) row <-> window-partitioned row
__device__ __forceinline__ int map_fwd(int r) {
    int b = r / 3136; int l = r - b * 3136;
    int hh = l / 56;  int ww = l - hh * 56;
    int win = (hh / 7) * 8 + (ww / 7);
    int n   = (hh % 7) * 7 + (ww % 7);
    return (b * 64 + win) * 49 + n;
}
__device__ __forceinline__ int map_inv(int wr) {
    int winG = wr / 49; int n = wr - winG * 49;
    int b = winG >> 6;  int w = winG & 63;
    int hh = (w >> 3) * 7 + n / 7;
    int ww = (w & 7) * 7 + (n % 7);
    return b * 3136 + hh * 56 + ww;
}

// ---------------- weight transpose+convert: in[K][N] f32 -> out[N][K] f16 ---
__global__ __launch_bounds__(256) void k_transpose(const float* __restrict__ in,
                                                   __half* __restrict__ out,
                                                   int K, int N) {
    __shared__ float t[32][33];
    int n0 = blockIdx.x * 32, k0 = blockIdx.y * 32;
    int tx = threadIdx.x & 31, ty = threadIdx.x >> 5;
#pragma unroll
    for (int i = 0; i < 4; i++)
        t[ty + i * 8][tx] = in[(size_t)(k0 + ty + i * 8) * N + n0 + tx];
    __syncthreads();
#pragma unroll
    for (int i = 0; i < 4; i++)
        out[(size_t)(n0 + ty + i * 8) * K + k0 + tx] = __float2half(t[tx][ty + i * 8]);
}

// ---------------- LayerNorm: f32 in -> f16 out (one block per row) ----------
template<bool PERM>
__global__ __launch_bounds__(128) void ln_kernel(const float* __restrict__ in,
                                                 const float* __restrict__ gamma,
                                                 const float* __restrict__ beta) {
    int row = blockIdx.x;
    int tid = threadIdx.x;
    const float4 v = *((const float4*)(in + (size_t)row * 512) + tid);
    float s = v.x + v.y + v.z + v.w;
    float q = v.x * v.x + v.y * v.y + v.z * v.z + v.w * v.w;
#pragma unroll
    for (int o = 16; o > 0; o >>= 1) {
        s += __shfl_xor_sync(0xffffffffu, s, o);
        q += __shfl_xor_sync(0xffffffffu, q, o);
    }
    __shared__ float red[8];
    int wid = tid >> 5;
    if ((tid & 31) == 0) { red[wid] = s; red[4 + wid] = q; }
    __syncthreads();
    s = red[0] + red[1] + red[2] + red[3];
    q = red[4] + red[5] + red[6] + red[7];
    float mu   = s * (1.0f / 512.0f);
    float var  = q * (1.0f / 512.0f) - mu * mu;
    float rstd = rsqrtf(var + 1e-5f);
    float4 g = *((const float4*)gamma + tid);
    float4 b = *((const float4*)beta + tid);
    float ox = (v.x - mu) * rstd * g.x + b.x;
    float oy = (v.y - mu) * rstd * g.y + b.y;
    float oz = (v.z - mu) * rstd * g.z + b.z;
    float ow = (v.w - mu) * rstd * g.w + b.w;
    int orow = PERM ? map_fwd(row) : row;
    __half2 h0 = __floats2half2_rn(ox, oy);
    __half2 h1 = __floats2half2_rn(oz, ow);
    *(uint2*)(g_hh + (size_t)orow * 512 + tid * 4) =
        make_uint2(*(unsigned*)&h0, *(unsigned*)&h1);
}

// ---------------- fp16 tensor-core GEMM -------------------------------------
// C[M x N] = A[M x K](f16, k-contig) @ Wt[N x K](f16, k-contig)^T + bias.
// Block 128x128x64, 256 thr = 8 warps (2m x 4n), warp 64x32.
// Smem rows: 64 halves = 128B = 8 x 16B chunks, xor-8 swizzle (chunk ^= row&7).
// EPI: 0=store f16  1=GELU f16  2=window-reverse+residual->dout f32  3=dout+=v
__device__ __forceinline__ void load_stage(const __half* __restrict__ A,
                                           const __half* __restrict__ Wt,
                                           int K, int rowBase, int colBase, int k0,
                                           uint32_t abase, int tid) {
#pragma unroll
    for (int i = 0; i < 4; i++) {
        int g = i * 256 + tid;
        int row = g >> 3, c = g & 7;
        int phys = c ^ (row & 7);
        cpa16(abase + (uint32_t)(row * 8 + phys) * 16u,
              A + (size_t)(rowBase + row) * K + k0 + c * 8);
    }
#pragma unroll
    for (int i = 0; i < 4; i++) {
        int g = i * 256 + tid;
        int row = g >> 3, c = g & 7;
        int phys = c ^ (row & 7);
        cpa16(abase + 16384u + (uint32_t)(row * 8 + phys) * 16u,
              Wt + (size_t)(colBase + row) * K + k0 + c * 8);
    }
}

template<int EPI>
__device__ void gemm_fp16(const __half* __restrict__ A, const __half* __restrict__ Wt,
                          const float* __restrict__ bias, __half* __restrict__ Ch,
                          const float* __restrict__ xres, float* __restrict__ dout,
                          int N, int K, int rowBase, int colBase) {
    extern __shared__ char smc[];
    uint32_t sb = (uint32_t)__cvta_generic_to_shared(smc);
    int tid = threadIdx.x, lane = tid & 31, wid = tid >> 5;
    int gid = lane >> 2, tig = lane & 3;
    int wm = wid & 1, wn = wid >> 1;
    int g8 = lane >> 3, lr = lane & 7;

    float acc[4][4][4];
#pragma unroll
    for (int a = 0; a < 4; a++)
#pragma unroll
        for (int b = 0; b < 4; b++)
#pragma unroll
            for (int c = 0; c < 4; c++) acc[a][b][c] = 0.f;

    const int S = K >> 6;
    load_stage(A, Wt, K, rowBase, colBase, 0, sb, tid);
    cpa_commit();

    for (int s = 0; s < S; s++) {
        uint32_t abase = sb + (uint32_t)(s & 1) * 32768u;
        if (s + 1 < S) {
            load_stage(A, Wt, K, rowBase, colBase, (s + 1) * 64,
                       sb + (uint32_t)((s + 1) & 1) * 32768u, tid);
            cpa_commit();
            cpa_wait<1>();
        } else {
            cpa_wait<0>();
        }
        __syncthreads();

        uint32_t bbase = abase + 16384u;
#pragma unroll
        for (int kt = 0; kt < 4; kt++) {
            unsigned af[4][4];
#pragma unroll
            for (int mt = 0; mt < 4; mt++) {
                int row = wm * 64 + mt * 16 + (g8 & 1) * 8 + lr;
                int phys = (kt * 2 + (g8 >> 1)) ^ lr;
                ldsm4(af[mt], abase + (uint32_t)(row * 8 + phys) * 16u);
            }
            unsigned bf[2][4];
#pragma unroll
            for (int ntp = 0; ntp < 2; ntp++) {
                int row = wn * 32 + ntp * 16 + (g8 >> 1) * 8 + lr;
                int phys = (kt * 2 + (g8 & 1)) ^ lr;
                ldsm4(bf[ntp], bbase + (uint32_t)(row * 8 + phys) * 16u);
            }
#pragma unroll
            for (int nt = 0; nt < 4; nt++) {
                int ntp = nt >> 1, hi = nt & 1;
                unsigned b0 = bf[ntp][hi * 2 + 0];
                unsigned b1 = bf[ntp][hi * 2 + 1];
#pragma unroll
                for (int mt = 0; mt < 4; mt++)
                    mma16(acc[mt][nt], af[mt], b0, b1);
            }
        }
        __syncthreads();
    }

    // epilogue
#pragma unroll
    for (int mt = 0; mt < 4; mt++) {
#pragma unroll
        for (int nt = 0; nt < 4; nt++) {
            int col = colBase + wn * 32 + nt * 8 + tig * 2;
            float b0v = bias[col], b1v = bias[col + 1];
#pragma unroll
            for (int h = 0; h < 2; h++) {
                int row = rowBase + wm * 64 + mt * 16 + gid + h * 8;
                float v0 = acc[mt][nt][h * 2 + 0] + b0v;
                float v1 = acc[mt][nt][h * 2 + 1] + b1v;
                if (EPI == 0) {
                    *(__half2*)(Ch + (size_t)row * N + col) = __floats2half2_rn(v0, v1);
                } else if (EPI == 1) {
                    float t0 = 0.5f * v0 * (1.0f + erff(v0 * INV_SQRT2));
                    float t1 = 0.5f * v1 * (1.0f + erff(v1 * INV_SQRT2));
                    *(__half2*)(Ch + (size_t)row * N + col) = __floats2half2_rn(t0, t1);
                } else if (EPI == 2) {
                    int r = map_inv(row);
                    size_t o = (size_t)r * 512 + col;
                    float2 xr = *(const float2*)(xres + o);
                    *(float2*)(dout + o) = make_float2(xr.x + v0, xr.y + v1);
                } else {
                    size_t o = (size_t)row * N + col;
                    float2 d = *(const float2*)(dout + o);
                    *(float2*)(dout + o) = make_float2(d.x + v0, d.y + v1);
                }
            }
        }
    }
}

// ---------------- GEMM wrappers --------------------------------------------
__global__ __launch_bounds__(256) void k_gemm_qkv(const float* __restrict__ bq,
                                                  const float* __restrict__ bk,
                                                  const float* __restrict__ bv) {
    int sel = blockIdx.x >> 2;
    const __half* Wt  = (sel == 0) ? g_wqt : ((sel == 1) ? g_wkt : g_wvt);
    const float* bias = (sel == 0) ? bq : ((sel == 1) ? bk : bv);
    __half* C         = (sel == 0) ? g_qh : ((sel == 1) ? g_kh : g_vh);
    gemm_fp16<0>(g_hh, Wt, bias, C, nullptr, nullptr, 512, 512,
                 blockIdx.y * 128, (blockIdx.x & 3) * 128);
}

__global__ __launch_bounds__(256) void k_gemm_proj(const float* __restrict__ bp,
                                                   const float* __restrict__ x,
                                                   float* __restrict__ dout) {
    gemm_fp16<2>(g_oh, g_wpt, bp, nullptr, x, dout, 512, 512,
                 blockIdx.y * 128, blockIdx.x * 128);
}

__global__ __launch_bounds__(256) void k_gemm_mlp1(const float* __restrict__ b1) {
    gemm_fp16<1>(g_hh, g_w1t, b1, g_hid, nullptr, nullptr, 2048, 512,
                 blockIdx.y * 128, blockIdx.x * 128);
}

__global__ __launch_bounds__(256) void k_gemm_mlp2(const float* __restrict__ b2,
                                                   float* __restrict__ dout) {
    gemm_fp16<3>(g_hid, g_w2t, b2, nullptr, nullptr, dout, 512, 2048,
                 blockIdx.y * 128, blockIdx.x * 128);
}

// ---------------- fused window attention (tf32 mma; fp16 I/O buffers) -------
__global__ __launch_bounds__(128) void k_attn(const float* __restrict__ relb) {
    __shared__ unsigned qs[64][36];
    __shared__ unsigned ks[56][36];
    __shared__ unsigned vs[56][40];
    __shared__ float    smx[64][60];
    int win = blockIdx.x, head = blockIdx.y;
    int tid = threadIdx.x;
    int wid = tid >> 5, lane = tid & 31;
    int gid = lane >> 2, tig = lane & 3;
    size_t base = ((size_t)win * 49) * 512 + head * 32;

    for (int i = tid; i < 64 * 32; i += 128) {
        int r = i >> 5, d = i & 31;
        float v = (r < 49) ? __half2float(g_qh[base + (size_t)r * 512 + d]) * SCALE_ATTN : 0.f;
        qs[r][d] = f2tf(v);
    }
    for (int i = tid; i < 56 * 32; i += 128) {
        int r = i >> 5, d = i & 31;
        float kv = (r < 49) ? __half2float(g_kh[base + (size_t)r * 512 + d]) : 0.f;
        ks[r][d] = f2tf(kv);
        float vv = (r < 49) ? __half2float(g_vh[base + (size_t)r * 512 + d]) : 0.f;
        vs[r][d] = f2tf(vv);
    }
    __syncthreads();

    int wr = wid * 16;
    {   // S = Q K^T
        float acc[7][4];
#pragma unroll
        for (int nt = 0; nt < 7; nt++)
#pragma unroll
            for (int e = 0; e < 4; e++) acc[nt][e] = 0.f;
#pragma unroll
        for (int kt = 0; kt < 4; kt++) {
            int k8 = kt * 8;
            unsigned a0 = qs[wr + gid][k8 + tig];
            unsigned a1 = qs[wr + gid + 8][k8 + tig];
            unsigned a2 = qs[wr + gid][k8 + tig + 4];
            unsigned a3 = qs[wr + gid + 8][k8 + tig + 4];
#pragma unroll
            for (int nt = 0; nt < 7; nt++) {
                unsigned b0 = ks[nt * 8 + gid][k8 + tig];
                unsigned b1 = ks[nt * 8 + gid][k8 + tig + 4];
                mma8(acc[nt], a0, a1, a2, a3, b0, b1);
            }
        }
        const float* bh = relb + head * 2401;
#pragma unroll
        for (int nt = 0; nt < 7; nt++)
#pragma unroll
            for (int e = 0; e < 4; e++) {
                int i = wr + gid + (e >> 1) * 8;
                int j = nt * 8 + tig * 2 + (e & 1);
                float v = acc[nt][e];
                if (j < 49) { if (i < 49) v += bh[i * 49 + j]; }
                else v = -1e30f;
                smx[i][j] = v;
            }
    }
    __syncwarp();
    for (int i = wr; i < wr + 16; i++) {
        float x0 = smx[i][lane];
        float x1 = (lane < 24) ? smx[i][lane + 32] : -1e30f;
        float m = fmaxf(x0, x1);
#pragma unroll
        for (int o = 16; o > 0; o >>= 1) m = fmaxf(m, __shfl_xor_sync(0xffffffffu, m, o));
        float e0 = expf(x0 - m);
        float e1 = (lane < 24) ? expf(x1 - m) : 0.f;
        float s = e0 + e1;
#pragma unroll
        for (int o = 16; o > 0; o >>= 1) s += __shfl_xor_sync(0xffffffffu, s, o);
        float inv = 1.0f / s;
        smx[i][lane] = e0 * inv;
        if (lane < 24) smx[i][lane + 32] = e1 * inv;
    }
    __syncwarp();
    {   // O = P V
        float acc[4][4];
#pragma unroll
        for (int nt = 0; nt < 4; nt++)
#pragma unroll
            for (int e = 0; e < 4; e++) acc[nt][e] = 0.f;
#pragma unroll
        for (int jt = 0; jt < 7; jt++) {
            int j8 = jt * 8;
            unsigned a0 = f2tf(smx[wr + gid][j8 + tig]);
            unsigned a1 = f2tf(smx[wr + gid + 8][j8 + tig]);
            unsigned a2 = f2tf(smx[wr + gid][j8 + tig + 4]);
            unsigned a3 = f2tf(smx[wr + gid + 8][j8 + tig + 4]);
#pragma unroll
            for (int nt = 0; nt < 4; nt++) {
                unsigned b0 = vs[j8 + tig][nt * 8 + gid];
                unsigned b1 = vs[j8 + tig + 4][nt * 8 + gid];
                mma8(acc[nt], a0, a1, a2, a3, b0, b1);
            }
        }
#pragma unroll
        for (int nt = 0; nt < 4; nt++)
#pragma unroll
            for (int e = 0; e < 4; e++) {
                int i = wr + gid + (e >> 1) * 8;
                int d = nt * 8 + tig * 2 + (e & 1);
                if (i < 49) g_oh[base + (size_t)i * 512 + d] = __float2half(acc[nt][e]);
            }
    }
}

// ---------------- launch ----------------------------------------------------
extern "C" void kernel_launch(void* const* d_in, const int* in_sizes, int n_in,
                              void* d_out, int out_size) {
    const float* x   = (const float*)d_in[0];
    const float* Wq  = (const float*)d_in[1];
    const float* bq  = (const float*)d_in[2];
    const float* Wk  = (const float*)d_in[3];
    const float* bk  = (const float*)d_in[4];
    const float* Wv  = (const float*)d_in[5];
    const float* bv  = (const float*)d_in[6];
    const float* Wp  = (const float*)d_in[7];
    const float* bp  = (const float*)d_in[8];
    const float* rb  = (const float*)d_in[9];
    const float* g1  = (const float*)d_in[10];
    const float* b1  = (const float*)d_in[11];
    const float* g2  = (const float*)d_in[12];
    const float* b2  = (const float*)d_in[13];
    const float* W1  = (const float*)d_in[14];
    const float* bf1 = (const float*)d_in[15];
    const float* W2  = (const float*)d_in[16];
    const float* bf2 = (const float*)d_in[17];
    float* out = (float*)d_out;

    cudaFuncSetAttribute(k_gemm_qkv,  cudaFuncAttributeMaxDynamicSharedMemorySize, SMEM_BYTES);
    cudaFuncSetAttribute(k_gemm_proj, cudaFuncAttributeMaxDynamicSharedMemorySize, SMEM_BYTES);
    cudaFuncSetAttribute(k_gemm_mlp1, cudaFuncAttributeMaxDynamicSharedMemorySize, SMEM_BYTES);
    cudaFuncSetAttribute(k_gemm_mlp2, cudaFuncAttributeMaxDynamicSharedMemorySize, SMEM_BYTES);

    // 0. pre-transpose + f16-convert weights (B operands, K-major)
    __half* wqt; cudaGetSymbolAddress((void**)&wqt, g_wqt);
    __half* wkt; cudaGetSymbolAddress((void**)&wkt, g_wkt);
    __half* wvt; cudaGetSymbolAddress((void**)&wvt, g_wvt);
    __half* wpt; cudaGetSymbolAddress((void**)&wpt, g_wpt);
    __half* w1t; cudaGetSymbolAddress((void**)&w1t, g_w1t);
    __half* w2t; cudaGetSymbolAddress((void**)&w2t, g_w2t);
    k_transpose<<<dim3(16, 16), 256>>>(Wq, wqt, 512, 512);
    k_transpose<<<dim3(16, 16), 256>>>(Wk, wkt, 512, 512);
    k_transpose<<<dim3(16, 16), 256>>>(Wv, wvt, 512, 512);
    k_transpose<<<dim3(16, 16), 256>>>(Wp, wpt, 512, 512);
    k_transpose<<<dim3(64, 16), 256>>>(W1, w1t, 512, 2048);
    k_transpose<<<dim3(16, 64), 256>>>(W2, w2t, 2048, 512);

    // 1. LN1 + window partition permute -> g_hh (f16, window order)
    ln_kernel<true><<<M_ROWS, 128>>>(x, g1, b1);
    // 2. Q/K/V projection (fp16 HMMA)
    k_gemm_qkv<<<dim3(12, 392), 256, SMEM_BYTES>>>(bq, bk, bv);
    // 3. windowed attention -> g_oh
    k_attn<<<dim3(1024, 16), 128>>>(rb);
    // 4. output projection + window reverse + residual -> d_out (f32)
    k_gemm_proj<<<dim3(4, 392), 256, SMEM_BYTES>>>(bp, x, out);
    // 5. LN2 -> g_hh (f16, row order)
    ln_kernel<false><<<M_ROWS, 128>>>(out, g2, b2);
    // 6. MLP fc1 + exact GELU -> g_hid (f16)
    k_gemm_mlp1<<<dim3(16, 392), 256, SMEM_BYTES>>>(bf1);
    // 7. MLP fc2 + residual add into d_out
    k_gemm_mlp2<<<dim3(4, 392), 256, SMEM_BYTES>>>(bf2, out);
}

// round 12
// speedup vs baseline: 2.8553x; 1.2788x over previous
#include <cuda_runtime.h>
#include <cuda_fp16.h>
#include <cstdint>

// Problem: B=16, H=W=56, C=512, WS=7, NH=16, HD=32, HID=2048, N=49, NW=64
#define M_ROWS 50176
#define SCALE_ATTN 0.17677669529663687f  // 32^-0.5
#define INV_SQRT2  0.70710678118654752f

// fp16 GEMM: block 128x256x64, 2-stage cp.async. Stage = A 16KB + B 32KB.
#define SMEM_BYTES 98304

// ---------------- scratch (static device allocations) ----------------------
__device__ __half g_hh[50176 * 512];      // LN1 out (window order) / LN2 out (rows)
__device__ __half g_qh[50176 * 512];
__device__ __half g_kh[50176 * 512];
__device__ __half g_vh[50176 * 512];
__device__ __half g_oh[50176 * 512];      // attention output
__device__ __half g_hid[50176 * 2048];
__device__ __half g_wqt[262144], g_wkt[262144], g_wvt[262144], g_wpt[262144];
__device__ __half g_w1t[1048576];         // [2048][512]
__device__ __half g_w2t[1048576];         // [512][2048]

// ---------------- helpers ---------------------------------------------------
__device__ __forceinline__ unsigned f2tf(float f) {
    unsigned u;
    asm("cvt.rna.tf32.f32 %0, %1;" : "=r"(u) : "f"(f));
    return u;
}

__device__ __forceinline__ void mma8(float c[4],
                                     unsigned a0, unsigned a1, unsigned a2, unsigned a3,
                                     unsigned b0, unsigned b1) {
    asm volatile(
        "mma.sync.aligned.m16n8k8.row.col.f32.tf32.tf32.f32 "
        "{%0,%1,%2,%3},{%4,%5,%6,%7},{%8,%9},{%0,%1,%2,%3};"
        : "+f"(c[0]), "+f"(c[1]), "+f"(c[2]), "+f"(c[3])
        : "r"(a0), "r"(a1), "r"(a2), "r"(a3), "r"(b0), "r"(b1));
}

__device__ __forceinline__ void mma16(float c[4], const unsigned a[4],
                                      unsigned b0, unsigned b1) {
    asm volatile(
        "mma.sync.aligned.m16n8k16.row.col.f32.f16.f16.f32 "
        "{%0,%1,%2,%3},{%4,%5,%6,%7},{%8,%9},{%0,%1,%2,%3};"
        : "+f"(c[0]), "+f"(c[1]), "+f"(c[2]), "+f"(c[3])
        : "r"(a[0]), "r"(a[1]), "r"(a[2]), "r"(a[3]), "r"(b0), "r"(b1));
}

__device__ __forceinline__ void ldsm4(unsigned r[4], uint32_t addr) {
    asm volatile("ldmatrix.sync.aligned.m8n8.x4.shared.b16 {%0,%1,%2,%3}, [%4];"
                 : "=r"(r[0]), "=r"(r[1]), "=r"(r[2]), "=r"(r[3]) : "r"(addr));
}

__device__ __forceinline__ void cpa16(uint32_t dst, const void* src) {
    asm volatile("cp.async.cg.shared.global [%0], [%1], 16;" :: "r"(dst), "l"(src));
}
__device__ __forceinline__ void cpa_commit() { asm volatile("cp.async.commit_group;"); }
template<int N>
__device__ __forceinline__ void cpa_wait() { asm volatile("cp.async.wait_group %0;" :: "n"(N)); }

// (b,l) row <-> window-partitioned row
__device__ __forceinline__ int map_fwd(int r) {
    int b = r / 3136; int l = r - b * 3136;
    int hh = l / 56;  int ww = l - hh * 56;
    int win = (hh / 7) * 8 + (ww / 7);
    int n   = (hh % 7) * 7 + (ww % 7);
    return (b * 64 + win) * 49 + n;
}
__device__ __forceinline__ int map_inv(int wr) {
    int winG = wr / 49; int n = wr - winG * 49;
    int b = winG >> 6;  int w = winG & 63;
    int hh = (w >> 3) * 7 + n / 7;
    int ww = (w & 7) * 7 + (n % 7);
    return b * 3136 + hh * 56 + ww;
}

// ---------------- batched weight transpose+convert --------------------------
// 4 square 512x512 weights in one launch (grid.z selects)
__global__ __launch_bounds__(256) void k_transpose4(const float* __restrict__ w0,
                                                    const float* __restrict__ w1,
                                                    const float* __restrict__ w2,
                                                    const float* __restrict__ w3) {
    __shared__ float t[32][33];
    int z = blockIdx.z;
    const float* in = (z == 0) ? w0 : (z == 1) ? w1 : (z == 2) ? w2 : w3;
    __half* out = (z == 0) ? g_wqt : (z == 1) ? g_wkt : (z == 2) ? g_wvt : g_wpt;
    const int K = 512, N = 512;
    int n0 = blockIdx.x * 32, k0 = blockIdx.y * 32;
    int tx = threadIdx.x & 31, ty = threadIdx.x >> 5;
#pragma unroll
    for (int i = 0; i < 4; i++)
        t[ty + i * 8][tx] = in[(size_t)(k0 + ty + i * 8) * N + n0 + tx];
    __syncthreads();
#pragma unroll
    for (int i = 0; i < 4; i++)
        out[(size_t)(n0 + ty + i * 8) * K + k0 + tx] = __float2half(t[tx][ty + i * 8]);
}

// W1 [512][2048] and W2 [2048][512] in one launch (grid (64,64,2), early-out)
__global__ __launch_bounds__(256) void k_transpose2(const float* __restrict__ W1,
                                                    const float* __restrict__ W2) {
    __shared__ float t[32][33];
    int z = blockIdx.z;
    const float* in = z ? W2 : W1;
    __half* out = z ? g_w2t : g_w1t;
    int K = z ? 2048 : 512, N = z ? 512 : 2048;
    int n0 = blockIdx.x * 32, k0 = blockIdx.y * 32;
    if (n0 >= N || k0 >= K) return;
    int tx = threadIdx.x & 31, ty = threadIdx.x >> 5;
#pragma unroll
    for (int i = 0; i < 4; i++)
        t[ty + i * 8][tx] = in[(size_t)(k0 + ty + i * 8) * N + n0 + tx];
    __syncthreads();
#pragma unroll
    for (int i = 0; i < 4; i++)
        out[(size_t)(n0 + ty + i * 8) * K + k0 + tx] = __float2half(t[tx][ty + i * 8]);
}

// ---------------- LayerNorm: f32 in -> f16 out (one block per row) ----------
template<bool PERM>
__global__ __launch_bounds__(128) void ln_kernel(const float* __restrict__ in,
                                                 const float* __restrict__ gamma,
                                                 const float* __restrict__ beta) {
    int row = blockIdx.x;
    int tid = threadIdx.x;
    const float4 v = *((const float4*)(in + (size_t)row * 512) + tid);
    float s = v.x + v.y + v.z + v.w;
    float q = v.x * v.x + v.y * v.y + v.z * v.z + v.w * v.w;
#pragma unroll
    for (int o = 16; o > 0; o >>= 1) {
        s += __shfl_xor_sync(0xffffffffu, s, o);
        q += __shfl_xor_sync(0xffffffffu, q, o);
    }
    __shared__ float red[8];
    int wid = tid >> 5;
    if ((tid & 31) == 0) { red[wid] = s; red[4 + wid] = q; }
    __syncthreads();
    s = red[0] + red[1] + red[2] + red[3];
    q = red[4] + red[5] + red[6] + red[7];
    float mu   = s * (1.0f / 512.0f);
    float var  = q * (1.0f / 512.0f) - mu * mu;
    float rstd = rsqrtf(var + 1e-5f);
    float4 g = *((const float4*)gamma + tid);
    float4 b = *((const float4*)beta + tid);
    float ox = (v.x - mu) * rstd * g.x + b.x;
    float oy = (v.y - mu) * rstd * g.y + b.y;
    float oz = (v.z - mu) * rstd * g.z + b.z;
    float ow = (v.w - mu) * rstd * g.w + b.w;
    int orow = PERM ? map_fwd(row) : row;
    __half2 h0 = __floats2half2_rn(ox, oy);
    __half2 h1 = __floats2half2_rn(oz, ow);
    *(uint2*)(g_hh + (size_t)orow * 512 + tid * 4) =
        make_uint2(*(unsigned*)&h0, *(unsigned*)&h1);
}

// ---------------- fp16 tensor-core GEMM -------------------------------------
// C[M x N] = A[M x K](f16, k-contig) @ Wt[N x K](f16, k-contig)^T + bias.
// Block 128x256x64, 256 thr = 8 warps (2m x 4n), warp 64x64.
// Smem rows: 64 halves = 128B = 8 x 16B chunks, xor-8 swizzle (chunk ^= row&7).
// Stage: A 16KB @ +0, B 32KB @ +16384.
// EPI: 0=store f16  1=GELU f16  2=window-reverse+residual->dout f32  3=dout+=v
__device__ __forceinline__ void load_stage(const __half* __restrict__ A,
                                           const __half* __restrict__ Wt,
                                           int K, int rowBase, int colBase, int k0,
                                           uint32_t abase, int tid) {
#pragma unroll
    for (int i = 0; i < 4; i++) {
        int g = i * 256 + tid;
        int row = g >> 3, c = g & 7;
        int phys = c ^ (row & 7);
        cpa16(abase + (uint32_t)(row * 8 + phys) * 16u,
              A + (size_t)(rowBase + row) * K + k0 + c * 8);
    }
#pragma unroll
    for (int i = 0; i < 8; i++) {
        int g = i * 256 + tid;
        int row = g >> 3, c = g & 7;
        int phys = c ^ (row & 7);
        cpa16(abase + 16384u + (uint32_t)(row * 8 + phys) * 16u,
              Wt + (size_t)(colBase + row) * K + k0 + c * 8);
    }
}

template<int EPI>
__device__ void gemm_fp16(const __half* __restrict__ A, const __half* __restrict__ Wt,
                          const float* __restrict__ bias, __half* __restrict__ Ch,
                          const float* __restrict__ xres, float* __restrict__ dout,
                          int N, int K, int rowBase, int colBase) {
    extern __shared__ char smc[];
    uint32_t sb = (uint32_t)__cvta_generic_to_shared(smc);
    int tid = threadIdx.x, lane = tid & 31, wid = tid >> 5;
    int gid = lane >> 2, tig = lane & 3;
    int wm = wid & 1, wn = wid >> 1;            // 2 x 4 warp grid
    int g8 = lane >> 3, lr = lane & 7;

    float acc[4][8][4];
#pragma unroll
    for (int a = 0; a < 4; a++)
#pragma unroll
        for (int b = 0; b < 8; b++)
#pragma unroll
            for (int c = 0; c < 4; c++) acc[a][b][c] = 0.f;

    const int S = K >> 6;
    load_stage(A, Wt, K, rowBase, colBase, 0, sb, tid);
    cpa_commit();

    for (int s = 0; s < S; s++) {
        uint32_t abase = sb + (uint32_t)(s & 1) * 49152u;
        if (s + 1 < S) {
            load_stage(A, Wt, K, rowBase, colBase, (s + 1) * 64,
                       sb + (uint32_t)((s + 1) & 1) * 49152u, tid);
            cpa_commit();
            cpa_wait<1>();
        } else {
            cpa_wait<0>();
        }
        __syncthreads();

        uint32_t bbase = abase + 16384u;
#pragma unroll
        for (int kt = 0; kt < 4; kt++) {
            unsigned af[4][4];
#pragma unroll
            for (int mt = 0; mt < 4; mt++) {
                int row = wm * 64 + mt * 16 + (g8 & 1) * 8 + lr;
                int phys = (kt * 2 + (g8 >> 1)) ^ lr;
                ldsm4(af[mt], abase + (uint32_t)(row * 8 + phys) * 16u);
            }
            unsigned bf[4][4];
#pragma unroll
            for (int ntp = 0; ntp < 4; ntp++) {
                int row = wn * 64 + ntp * 16 + (g8 >> 1) * 8 + lr;
                int phys = (kt * 2 + (g8 & 1)) ^ lr;
                ldsm4(bf[ntp], bbase + (uint32_t)(row * 8 + phys) * 16u);
            }
#pragma unroll
            for (int nt = 0; nt < 8; nt++) {
                int ntp = nt >> 1, hi = nt & 1;
                unsigned b0 = bf[ntp][hi * 2 + 0];
                unsigned b1 = bf[ntp][hi * 2 + 1];
#pragma unroll
                for (int mt = 0; mt < 4; mt++)
                    mma16(acc[mt][nt], af[mt], b0, b1);
            }
        }
        __syncthreads();
    }

    // epilogue
#pragma unroll
    for (int mt = 0; mt < 4; mt++) {
#pragma unroll
        for (int nt = 0; nt < 8; nt++) {
            int col = colBase + wn * 64 + nt * 8 + tig * 2;
            float b0v = bias[col], b1v = bias[col + 1];
#pragma unroll
            for (int h = 0; h < 2; h++) {
                int row = rowBase + wm * 64 + mt * 16 + gid + h * 8;
                float v0 = acc[mt][nt][h * 2 + 0] + b0v;
                float v1 = acc[mt][nt][h * 2 + 1] + b1v;
                if (EPI == 0) {
                    *(__half2*)(Ch + (size_t)row * N + col) = __floats2half2_rn(v0, v1);
                } else if (EPI == 1) {
                    float t0 = 0.5f * v0 * (1.0f + erff(v0 * INV_SQRT2));
                    float t1 = 0.5f * v1 * (1.0f + erff(v1 * INV_SQRT2));
                    *(__half2*)(Ch + (size_t)row * N + col) = __floats2half2_rn(t0, t1);
                } else if (EPI == 2) {
                    int r = map_inv(row);
                    size_t o = (size_t)r * 512 + col;
                    float2 xr = *(const float2*)(xres + o);
                    *(float2*)(dout + o) = make_float2(xr.x + v0, xr.y + v1);
                } else {
                    size_t o = (size_t)row * N + col;
                    float2 d = *(const float2*)(dout + o);
                    *(float2*)(dout + o) = make_float2(d.x + v0, d.y + v1);
                }
            }
        }
    }
}

// ---------------- GEMM wrappers --------------------------------------------
__global__ __launch_bounds__(256) void k_gemm_qkv(const float* __restrict__ bq,
                                                  const float* __restrict__ bk,
                                                  const float* __restrict__ bv) {
    int sel = blockIdx.x >> 1;
    const __half* Wt  = (sel == 0) ? g_wqt : ((sel == 1) ? g_wkt : g_wvt);
    const float* bias = (sel == 0) ? bq : ((sel == 1) ? bk : bv);
    __half* C         = (sel == 0) ? g_qh : ((sel == 1) ? g_kh : g_vh);
    gemm_fp16<0>(g_hh, Wt, bias, C, nullptr, nullptr, 512, 512,
                 blockIdx.y * 128, (blockIdx.x & 1) * 256);
}

__global__ __launch_bounds__(256) void k_gemm_proj(const float* __restrict__ bp,
                                                   const float* __restrict__ x,
                                                   float* __restrict__ dout) {
    gemm_fp16<2>(g_oh, g_wpt, bp, nullptr, x, dout, 512, 512,
                 blockIdx.y * 128, blockIdx.x * 256);
}

__global__ __launch_bounds__(256) void k_gemm_mlp1(const float* __restrict__ b1) {
    gemm_fp16<1>(g_hh, g_w1t, b1, g_hid, nullptr, nullptr, 2048, 512,
                 blockIdx.y * 128, blockIdx.x * 256);
}

__global__ __launch_bounds__(256) void k_gemm_mlp2(const float* __restrict__ b2,
                                                   float* __restrict__ dout) {
    gemm_fp16<3>(g_hid, g_w2t, b2, nullptr, nullptr, dout, 512, 2048,
                 blockIdx.y * 128, blockIdx.x * 256);
}

// ---------------- fused window attention (tf32 mma; fp16 I/O buffers) -------
__global__ __launch_bounds__(128) void k_attn(const float* __restrict__ relb) {
    __shared__ unsigned qs[64][36];
    __shared__ unsigned ks[56][36];
    __shared__ unsigned vs[56][40];
    __shared__ float    smx[64][60];
    int win = blockIdx.x, head = blockIdx.y;
    int tid = threadIdx.x;
    int wid = tid >> 5, lane = tid & 31;
    int gid = lane >> 2, tig = lane & 3;
    size_t base = ((size_t)win * 49) * 512 + head * 32;

    for (int i = tid; i < 64 * 32; i += 128) {
        int r = i >> 5, d = i & 31;
        float v = (r < 49) ? __half2float(g_qh[base + (size_t)r * 512 + d]) * SCALE_ATTN : 0.f;
        qs[r][d] = f2tf(v);
    }
    for (int i = tid; i < 56 * 32; i += 128) {
        int r = i >> 5, d = i & 31;
        float kv = (r < 49) ? __half2float(g_kh[base + (size_t)r * 512 + d]) : 0.f;
        ks[r][d] = f2tf(kv);
        float vv = (r < 49) ? __half2float(g_vh[base + (size_t)r * 512 + d]) : 0.f;
        vs[r][d] = f2tf(vv);
    }
    __syncthreads();

    int wr = wid * 16;
    {   // S = Q K^T
        float acc[7][4];
#pragma unroll
        for (int nt = 0; nt < 7; nt++)
#pragma unroll
            for (int e = 0; e < 4; e++) acc[nt][e] = 0.f;
#pragma unroll
        for (int kt = 0; kt < 4; kt++) {
            int k8 = kt * 8;
            unsigned a0 = qs[wr + gid][k8 + tig];
            unsigned a1 = qs[wr + gid + 8][k8 + tig];
            unsigned a2 = qs[wr + gid][k8 + tig + 4];
            unsigned a3 = qs[wr + gid + 8][k8 + tig + 4];
#pragma unroll
            for (int nt = 0; nt < 7; nt++) {
                unsigned b0 = ks[nt * 8 + gid][k8 + tig];
                unsigned b1 = ks[nt * 8 + gid][k8 + tig + 4];
                mma8(acc[nt], a0, a1, a2, a3, b0, b1);
            }
        }
        const float* bh = relb + head * 2401;
#pragma unroll
        for (int nt = 0; nt < 7; nt++)
#pragma unroll
            for (int e = 0; e < 4; e++) {
                int i = wr + gid + (e >> 1) * 8;
                int j = nt * 8 + tig * 2 + (e & 1);
                float v = acc[nt][e];
                if (j < 49) { if (i < 49) v += bh[i * 49 + j]; }
                else v = -1e30f;
                smx[i][j] = v;
            }
    }
    __syncwarp();
    for (int i = wr; i < wr + 16; i++) {
        float x0 = smx[i][lane];
        float x1 = (lane < 24) ? smx[i][lane + 32] : -1e30f;
        float m = fmaxf(x0, x1);
#pragma unroll
        for (int o = 16; o > 0; o >>= 1) m = fmaxf(m, __shfl_xor_sync(0xffffffffu, m, o));
        float e0 = expf(x0 - m);
        float e1 = (lane < 24) ? expf(x1 - m) : 0.f;
        float s = e0 + e1;
#pragma unroll
        for (int o = 16; o > 0; o >>= 1) s += __shfl_xor_sync(0xffffffffu, s, o);
        float inv = 1.0f / s;
        smx[i][lane] = e0 * inv;
        if (lane < 24) smx[i][lane + 32] = e1 * inv;
    }
    __syncwarp();
    {   // O = P V
        float acc[4][4];
#pragma unroll
        for (int nt = 0; nt < 4; nt++)
#pragma unroll
            for (int e = 0; e < 4; e++) acc[nt][e] = 0.f;
#pragma unroll
        for (int jt = 0; jt < 7; jt++) {
            int j8 = jt * 8;
            unsigned a0 = f2tf(smx[wr + gid][j8 + tig]);
            unsigned a1 = f2tf(smx[wr + gid + 8][j8 + tig]);
            unsigned a2 = f2tf(smx[wr + gid][j8 + tig + 4]);
            unsigned a3 = f2tf(smx[wr + gid + 8][j8 + tig + 4]);
#pragma unroll
            for (int nt = 0; nt < 4; nt++) {
                unsigned b0 = vs[j8 + tig][nt * 8 + gid];
                unsigned b1 = vs[j8 + tig + 4][nt * 8 + gid];
                mma8(acc[nt], a0, a1, a2, a3, b0, b1);
            }
        }
#pragma unroll
        for (int nt = 0; nt < 4; nt++)
#pragma unroll
            for (int e = 0; e < 4; e++) {
                int i = wr + gid + (e >> 1) * 8;
                int d = nt * 8 + tig * 2 + (e & 1);
                if (i < 49) g_oh[base + (size_t)i * 512 + d] = __float2half(acc[nt][e]);
            }
    }
}

// ---------------- launch ----------------------------------------------------
extern "C" void kernel_launch(void* const* d_in, const int* in_sizes, int n_in,
                              void* d_out, int out_size) {
    const float* x   = (const float*)d_in[0];
    const float* Wq  = (const float*)d_in[1];
    const float* bq  = (const float*)d_in[2];
    const float* Wk  = (const float*)d_in[3];
    const float* bk  = (const float*)d_in[4];
    const float* Wv  = (const float*)d_in[5];
    const float* bv  = (const float*)d_in[6];
    const float* Wp  = (const float*)d_in[7];
    const float* bp  = (const float*)d_in[8];
    const float* rb  = (const float*)d_in[9];
    const float* g1  = (const float*)d_in[10];
    const float* b1  = (const float*)d_in[11];
    const float* g2  = (const float*)d_in[12];
    const float* b2  = (const float*)d_in[13];
    const float* W1  = (const float*)d_in[14];
    const float* bf1 = (const float*)d_in[15];
    const float* W2  = (const float*)d_in[16];
    const float* bf2 = (const float*)d_in[17];
    float* out = (float*)d_out;

    cudaFuncSetAttribute(k_gemm_qkv,  cudaFuncAttributeMaxDynamicSharedMemorySize, SMEM_BYTES);
    cudaFuncSetAttribute(k_gemm_proj, cudaFuncAttributeMaxDynamicSharedMemorySize, SMEM_BYTES);
    cudaFuncSetAttribute(k_gemm_mlp1, cudaFuncAttributeMaxDynamicSharedMemorySize, SMEM_BYTES);
    cudaFuncSetAttribute(k_gemm_mlp2, cudaFuncAttributeMaxDynamicSharedMemorySize, SMEM_BYTES);

    // 0. batched pre-transpose + f16 convert (2 launches; keeps ncu idx5 on proj)
    k_transpose4<<<dim3(16, 16, 4), 256>>>(Wq, Wk, Wv, Wp);
    k_transpose2<<<dim3(64, 64, 2), 256>>>(W1, W2);
    // 1. LN1 + window partition permute -> g_hh (f16, window order)
    ln_kernel<true><<<M_ROWS, 128>>>(x, g1, b1);
    // 2. Q/K/V projection (fp16 HMMA, 128x256 tiles)
    k_gemm_qkv<<<dim3(6, 392), 256, SMEM_BYTES>>>(bq, bk, bv);
    // 3. windowed attention -> g_oh
    k_attn<<<dim3(1024, 16), 128>>>(rb);
    // 4. output projection + window reverse + residual -> d_out (f32)  [ncu idx 5]
    k_gemm_proj<<<dim3(2, 392), 256, SMEM_BYTES>>>(bp, x, out);
    // 5. LN2 -> g_hh (f16, row order)
    ln_kernel<false><<<M_ROWS, 128>>>(out, g2, b2);
    // 6. MLP fc1 + exact GELU -> g_hid (f16)
    k_gemm_mlp1<<<dim3(8, 392), 256, SMEM_BYTES>>>(bf1);
    // 7. MLP fc2 + residual add into d_out
    k_gemm_mlp2<<<dim3(2, 392), 256, SMEM_BYTES>>>(bf2, out);
}

// round 15
// speedup vs baseline: 3.1710x; 1.1106x over previous
#include <cuda_runtime.h>
#include <cuda_fp16.h>
#include <cstdint>

// Problem: B=16, H=W=56, C=512, WS=7, NH=16, HD=32, HID=2048, N=49, NW=64
#define M_ROWS 50176
#define SCALE_ATTN 0.17677669529663687f  // 32^-0.5
#define INV_SQRT2  0.70710678118654752f

// fp16 GEMM: block 128x256x64, 3-stage cp.async. Stage = A 16KB + B 32KB.
#define STAGE_BYTES 49152u
#define SMEM_BYTES  147456

// ---------------- scratch (static device allocations) ----------------------
__device__ __half g_hh[50176 * 512];      // LN1 out (window order) / LN2 out (rows)
__device__ __half g_qh[50176 * 512];
__device__ __half g_kh[50176 * 512];
__device__ __half g_vh[50176 * 512];
__device__ __half g_oh[50176 * 512];      // attention output
__device__ __half g_hid[50176 * 2048];
__device__ __half g_wqt[262144], g_wkt[262144], g_wvt[262144], g_wpt[262144];
__device__ __half g_w1t[1048576];         // [2048][512]
__device__ __half g_w2t[1048576];         // [512][2048]

// ---------------- helpers ---------------------------------------------------
__device__ __forceinline__ unsigned f2tf(float f) {
    unsigned u;
    asm("cvt.rna.tf32.f32 %0, %1;" : "=r"(u) : "f"(f));
    return u;
}

__device__ __forceinline__ void mma8(float c[4],
                                     unsigned a0, unsigned a1, unsigned a2, unsigned a3,
                                     unsigned b0, unsigned b1) {
    asm volatile(
        "mma.sync.aligned.m16n8k8.row.col.f32.tf32.tf32.f32 "
        "{%0,%1,%2,%3},{%4,%5,%6,%7},{%8,%9},{%0,%1,%2,%3};"
        : "+f"(c[0]), "+f"(c[1]), "+f"(c[2]), "+f"(c[3])
        : "r"(a0), "r"(a1), "r"(a2), "r"(a3), "r"(b0), "r"(b1));
}

__device__ __forceinline__ void mma16(float c[4], const unsigned a[4],
                                      unsigned b0, unsigned b1) {
    asm volatile(
        "mma.sync.aligned.m16n8k16.row.col.f32.f16.f16.f32 "
        "{%0,%1,%2,%3},{%4,%5,%6,%7},{%8,%9},{%0,%1,%2,%3};"
        : "+f"(c[0]), "+f"(c[1]), "+f"(c[2]), "+f"(c[3])
        : "r"(a[0]), "r"(a[1]), "r"(a[2]), "r"(a[3]), "r"(b0), "r"(b1));
}

__device__ __forceinline__ void ldsm4(unsigned r[4], uint32_t addr) {
    asm volatile("ldmatrix.sync.aligned.m8n8.x4.shared.b16 {%0,%1,%2,%3}, [%4];"
                 : "=r"(r[0]), "=r"(r[1]), "=r"(r[2]), "=r"(r[3]) : "r"(addr));
}

__device__ __forceinline__ void cpa16(uint32_t dst, const void* src) {
    asm volatile("cp.async.cg.shared.global [%0], [%1], 16;" :: "r"(dst), "l"(src));
}
__device__ __forceinline__ void cpa_commit() { asm volatile("cp.async.commit_group;"); }
template<int N>
__device__ __forceinline__ void cpa_wait() { asm volatile("cp.async.wait_group %0;" :: "n"(N)); }

// (b,l) row <-> window-partitioned row
__device__ __forceinline__ int map_fwd(int r) {
    int b = r / 3136; int l = r - b * 3136;
    int hh = l / 56;  int ww = l - hh * 56;
    int win = (hh / 7) * 8 + (ww / 7);
    int n   = (hh % 7) * 7 + (ww % 7);
    return (b * 64 + win) * 49 + n;
}
__device__ __forceinline__ int map_inv(int wr) {
    int winG = wr / 49; int n = wr - winG * 49;
    int b = winG >> 6;  int w = winG & 63;
    int hh = (w >> 3) * 7 + n / 7;
    int ww = (w & 7) * 7 + (n % 7);
    return b * 3136 + hh * 56 + ww;
}

// ---------------- batched weight transpose+convert --------------------------
__global__ __launch_bounds__(256) void k_transpose4(const float* __restrict__ w0,
                                                    const float* __restrict__ w1,
                                                    const float* __restrict__ w2,
                                                    const float* __restrict__ w3) {
    __shared__ float t[32][33];
    int z = blockIdx.z;
    const float* in = (z == 0) ? w0 : (z == 1) ? w1 : (z == 2) ? w2 : w3;
    __half* out = (z == 0) ? g_wqt : (z == 1) ? g_wkt : (z == 2) ? g_wvt : g_wpt;
    const int K = 512, N = 512;
    int n0 = blockIdx.x * 32, k0 = blockIdx.y * 32;
    int tx = threadIdx.x & 31, ty = threadIdx.x >> 5;
#pragma unroll
    for (int i = 0; i < 4; i++)
        t[ty + i * 8][tx] = in[(size_t)(k0 + ty + i * 8) * N + n0 + tx];
    __syncthreads();
#pragma unroll
    for (int i = 0; i < 4; i++)
        out[(size_t)(n0 + ty + i * 8) * K + k0 + tx] = __float2half(t[tx][ty + i * 8]);
}

__global__ __launch_bounds__(256) void k_transpose2(const float* __restrict__ W1,
                                                    const float* __restrict__ W2) {
    __shared__ float t[32][33];
    int z = blockIdx.z;
    const float* in = z ? W2 : W1;
    __half* out = z ? g_w2t : g_w1t;
    int K = z ? 2048 : 512, N = z ? 512 : 2048;
    int n0 = blockIdx.x * 32, k0 = blockIdx.y * 32;
    if (n0 >= N || k0 >= K) return;
    int tx = threadIdx.x & 31, ty = threadIdx.x >> 5;
#pragma unroll
    for (int i = 0; i < 4; i++)
        t[ty + i * 8][tx] = in[(size_t)(k0 + ty + i * 8) * N + n0 + tx];
    __syncthreads();
#pragma unroll
    for (int i = 0; i < 4; i++)
        out[(size_t)(n0 + ty + i * 8) * K + k0 + tx] = __float2half(t[tx][ty + i * 8]);
}

// ---------------- LayerNorm: f32 in -> f16 out (one block per row) ----------
template<bool PERM>
__global__ __launch_bounds__(128) void ln_kernel(const float* __restrict__ in,
                                                 const float* __restrict__ gamma,
                                                 const float* __restrict__ beta) {
    int row = blockIdx.x;
    int tid = threadIdx.x;
    const float4 v = *((const float4*)(in + (size_t)row * 512) + tid);
    float s = v.x + v.y + v.z + v.w;
    float q = v.x * v.x + v.y * v.y + v.z * v.z + v.w * v.w;
#pragma unroll
    for (int o = 16; o > 0; o >>= 1) {
        s += __shfl_xor_sync(0xffffffffu, s, o);
        q += __shfl_xor_sync(0xffffffffu, q, o);
    }
    __shared__ float red[8];
    int wid = tid >> 5;
    if ((tid & 31) == 0) { red[wid] = s; red[4 + wid] = q; }
    __syncthreads();
    s = red[0] + red[1] + red[2] + red[3];
    q = red[4] + red[5] + red[6] + red[7];
    float mu   = s * (1.0f / 512.0f);
    float var  = q * (1.0f / 512.0f) - mu * mu;
    float rstd = rsqrtf(var + 1e-5f);
    float4 g = *((const float4*)gamma + tid);
    float4 b = *((const float4*)beta + tid);
    float ox = (v.x - mu) * rstd * g.x + b.x;
    float oy = (v.y - mu) * rstd * g.y + b.y;
    float oz = (v.z - mu) * rstd * g.z + b.z;
    float ow = (v.w - mu) * rstd * g.w + b.w;
    int orow = PERM ? map_fwd(row) : row;
    __half2 h0 = __floats2half2_rn(ox, oy);
    __half2 h1 = __floats2half2_rn(oz, ow);
    *(uint2*)(g_hh + (size_t)orow * 512 + tid * 4) =
        make_uint2(*(unsigned*)&h0, *(unsigned*)&h1);
}

// ---------------- fp16 tensor-core GEMM -------------------------------------
// Block 128x256x64, 256 thr = 8 warps (2m x 4n), warp 64x64.
// 3-stage cp.async pipeline, ONE __syncthreads per stage.
// Smem rows: 64 halves = 128B = 8 x 16B chunks, xor-8 swizzle.
// EPI: 0=store f16  1=GELU f16  2=window-reverse+residual->dout f32  3=dout+=v
__device__ __forceinline__ void load_stage(const __half* __restrict__ A,
                                           const __half* __restrict__ Wt,
                                           int K, int rowBase, int colBase, int k0,
                                           uint32_t abase, int tid) {
#pragma unroll
    for (int i = 0; i < 4; i++) {
        int g = i * 256 + tid;
        int row = g >> 3, c = g & 7;
        int phys = c ^ (row & 7);
        cpa16(abase + (uint32_t)(row * 8 + phys) * 16u,
              A + (size_t)(rowBase + row) * K + k0 + c * 8);
    }
#pragma unroll
    for (int i = 0; i < 8; i++) {
        int g = i * 256 + tid;
        int row = g >> 3, c = g & 7;
        int phys = c ^ (row & 7);
        cpa16(abase + 16384u + (uint32_t)(row * 8 + phys) * 16u,
              Wt + (size_t)(colBase + row) * K + k0 + c * 8);
    }
}

template<int EPI>
__device__ void gemm_fp16(const __half* __restrict__ A, const __half* __restrict__ Wt,
                          const float* __restrict__ bias, __half* __restrict__ Ch,
                          const float* __restrict__ xres, float* __restrict__ dout,
                          int N, int K, int rowBase, int colBase) {
    extern __shared__ char smc[];
    uint32_t sb = (uint32_t)__cvta_generic_to_shared(smc);
    int tid = threadIdx.x, lane = tid & 31, wid = tid >> 5;
    int gid = lane >> 2, tig = lane & 3;
    int wm = wid & 1, wn = wid >> 1;            // 2 x 4 warp grid
    int g8 = lane >> 3, lr = lane & 7;

    float acc[4][8][4];
#pragma unroll
    for (int a = 0; a < 4; a++)
#pragma unroll
        for (int b = 0; b < 8; b++)
#pragma unroll
            for (int c = 0; c < 4; c++) acc[a][b][c] = 0.f;

    const int S = K >> 6;
    load_stage(A, Wt, K, rowBase, colBase, 0, sb, tid);
    cpa_commit();
    if (S > 1) {
        load_stage(A, Wt, K, rowBase, colBase, 64, sb + STAGE_BYTES, tid);
        cpa_commit();
    }

    int bufc = 0;  // (s % 3) tracked incrementally
    for (int s = 0; s < S; s++) {
        if (s + 1 < S) cpa_wait<1>(); else cpa_wait<0>();
        __syncthreads();   // stage s data visible to all; all warps done reading buf (s-1)%3
        if (s + 2 < S) {
            int nb = bufc + 2; if (nb >= 3) nb -= 3;
            load_stage(A, Wt, K, rowBase, colBase, (s + 2) * 64,
                       sb + (uint32_t)nb * STAGE_BYTES, tid);
            cpa_commit();
        }
        uint32_t abase = sb + (uint32_t)bufc * STAGE_BYTES;
        uint32_t bbase = abase + 16384u;
#pragma unroll
        for (int kt = 0; kt < 4; kt++) {
            unsigned af[4][4];
#pragma unroll
            for (int mt = 0; mt < 4; mt++) {
                int row = wm * 64 + mt * 16 + (g8 & 1) * 8 + lr;
                int phys = (kt * 2 + (g8 >> 1)) ^ lr;
                ldsm4(af[mt], abase + (uint32_t)(row * 8 + phys) * 16u);
            }
            unsigned bf[4][4];
#pragma unroll
            for (int ntp = 0; ntp < 4; ntp++) {
                int row = wn * 64 + ntp * 16 + (g8 >> 1) * 8 + lr;
                int phys = (kt * 2 + (g8 & 1)) ^ lr;
                ldsm4(bf[ntp], bbase + (uint32_t)(row * 8 + phys) * 16u);
            }
#pragma unroll
            for (int nt = 0; nt < 8; nt++) {
                int ntp = nt >> 1, hi = nt & 1;
                unsigned b0 = bf[ntp][hi * 2 + 0];
                unsigned b1 = bf[ntp][hi * 2 + 1];
#pragma unroll
                for (int mt = 0; mt < 4; mt++)
                    mma16(acc[mt][nt], af[mt], b0, b1);
            }
        }
        if (++bufc == 3) bufc = 0;
    }

    // epilogue
#pragma unroll
    for (int mt = 0; mt < 4; mt++) {
#pragma unroll
        for (int nt = 0; nt < 8; nt++) {
            int col = colBase + wn * 64 + nt * 8 + tig * 2;
            float b0v = bias[col], b1v = bias[col + 1];
#pragma unroll
            for (int h = 0; h < 2; h++) {
                int row = rowBase + wm * 64 + mt * 16 + gid + h * 8;
                float v0 = acc[mt][nt][h * 2 + 0] + b0v;
                float v1 = acc[mt][nt][h * 2 + 1] + b1v;
                if (EPI == 0) {
                    *(__half2*)(Ch + (size_t)row * N + col) = __floats2half2_rn(v0, v1);
                } else if (EPI == 1) {
                    float t0 = 0.5f * v0 * (1.0f + erff(v0 * INV_SQRT2));
                    float t1 = 0.5f * v1 * (1.0f + erff(v1 * INV_SQRT2));
                    *(__half2*)(Ch + (size_t)row * N + col) = __floats2half2_rn(t0, t1);
                } else if (EPI == 2) {
                    int r = map_inv(row);
                    size_t o = (size_t)r * 512 + col;
                    float2 xr = *(const float2*)(xres + o);
                    *(float2*)(dout + o) = make_float2(xr.x + v0, xr.y + v1);
                } else {
                    size_t o = (size_t)row * N + col;
                    float2 d = *(const float2*)(dout + o);
                    *(float2*)(dout + o) = make_float2(d.x + v0, d.y + v1);
                }
            }
        }
    }
}

// ---------------- GEMM wrappers --------------------------------------------
__global__ __launch_bounds__(256) void k_gemm_qkv(const float* __restrict__ bq,
                                                  const float* __restrict__ bk,
                                                  const float* __restrict__ bv) {
    int sel = blockIdx.x >> 1;
    const __half* Wt  = (sel == 0) ? g_wqt : ((sel == 1) ? g_wkt : g_wvt);
    const float* bias = (sel == 0) ? bq : ((sel == 1) ? bk : bv);
    __half* C         = (sel == 0) ? g_qh : ((sel == 1) ? g_kh : g_vh);
    gemm_fp16<0>(g_hh, Wt, bias, C, nullptr, nullptr, 512, 512,
                 blockIdx.y * 128, (blockIdx.x & 1) * 256);
}

__global__ __launch_bounds__(256) void k_gemm_proj(const float* __restrict__ bp,
                                                   const float* __restrict__ x,
                                                   float* __restrict__ dout) {
    gemm_fp16<2>(g_oh, g_wpt, bp, nullptr, x, dout, 512, 512,
                 blockIdx.y * 128, blockIdx.x * 256);
}

__global__ __launch_bounds__(256) void k_gemm_mlp1(const float* __restrict__ b1) {
    gemm_fp16<1>(g_hh, g_w1t, b1, g_hid, nullptr, nullptr, 2048, 512,
                 blockIdx.y * 128, blockIdx.x * 256);
}

__global__ __launch_bounds__(256) void k_gemm_mlp2(const float* __restrict__ b2,
                                                   float* __restrict__ dout) {
    gemm_fp16<3>(g_hid, g_w2t, b2, nullptr, nullptr, dout, 512, 2048,
                 blockIdx.y * 128, blockIdx.x * 256);
}

// ---------------- fused window attention (tf32 mma; fp16 I/O, vector loads) -
__global__ __launch_bounds__(128) void k_attn(const float* __restrict__ relb) {
    __shared__ unsigned qs[64][36];
    __shared__ unsigned ks[56][36];
    __shared__ unsigned vs[56][40];
    __shared__ float    smx[64][60];
    int win = blockIdx.x, head = blockIdx.y;
    int tid = threadIdx.x;
    int wid = tid >> 5, lane = tid & 31;
    int gid = lane >> 2, tig = lane & 3;
    size_t base = ((size_t)win * 49) * 512 + head * 32;

    // vectorized loads: 4 lanes x 16B cover one row's 32-half slice
    {
        int rr = tid >> 2, cc = (tid & 3) * 8;
#pragma unroll
        for (int p = 0; p < 2; p++) {
            int r = p * 32 + rr;
            uint4 raw = make_uint4(0u, 0u, 0u, 0u);
            if (r < 49) raw = *(const uint4*)(g_qh + base + (size_t)r * 512 + cc);
            const __half* hp = (const __half*)&raw;
#pragma unroll
            for (int j = 0; j < 8; j++)
                qs[r][cc + j] = f2tf(__half2float(hp[j]) * SCALE_ATTN);
        }
#pragma unroll
        for (int p = 0; p < 2; p++) {
            int r = p * 32 + rr;
            if (r < 56) {
                uint4 kraw = make_uint4(0u, 0u, 0u, 0u);
                uint4 vraw = make_uint4(0u, 0u, 0u, 0u);
                if (r < 49) {
                    kraw = *(const uint4*)(g_kh + base + (size_t)r * 512 + cc);
                    vraw = *(const uint4*)(g_vh + base + (size_t)r * 512 + cc);
                }
                const __half* kp = (const __half*)&kraw;
                const __half* vp = (const __half*)&vraw;
#pragma unroll
                for (int j = 0; j < 8; j++) {
                    ks[r][cc + j] = f2tf(__half2float(kp[j]));
                    vs[r][cc + j] = f2tf(__half2float(vp[j]));
                }
            }
        }
    }
    __syncthreads();

    int wr = wid * 16;
    {   // S = Q K^T
        float acc[7][4];
#pragma unroll
        for (int nt = 0; nt < 7; nt++)
#pragma unroll
            for (int e = 0; e < 4; e++) acc[nt][e] = 0.f;
#pragma unroll
        for (int kt = 0; kt < 4; kt++) {
            int k8 = kt * 8;
            unsigned a0 = qs[wr + gid][k8 + tig];
            unsigned a1 = qs[wr + gid + 8][k8 + tig];
            unsigned a2 = qs[wr + gid][k8 + tig + 4];
            unsigned a3 = qs[wr + gid + 8][k8 + tig + 4];
#pragma unroll
            for (int nt = 0; nt < 7; nt++) {
                unsigned b0 = ks[nt * 8 + gid][k8 + tig];
                unsigned b1 = ks[nt * 8 + gid][k8 + tig + 4];
                mma8(acc[nt], a0, a1, a2, a3, b0, b1);
            }
        }
        const float* bh = relb + head * 2401;
#pragma unroll
        for (int nt = 0; nt < 7; nt++)
#pragma unroll
            for (int e = 0; e < 4; e++) {
                int i = wr + gid + (e >> 1) * 8;
                int j = nt * 8 + tig * 2 + (e & 1);
                float v = acc[nt][e];
                if (j < 49) { if (i < 49) v += bh[i * 49 + j]; }
                else v = -1e30f;
                smx[i][j] = v;
            }
    }
    __syncwarp();
    for (int i = wr; i < wr + 16; i++) {
        float x0 = smx[i][lane];
        float x1 = (lane < 24) ? smx[i][lane + 32] : -1e30f;
        float m = fmaxf(x0, x1);
#pragma unroll
        for (int o = 16; o > 0; o >>= 1) m = fmaxf(m, __shfl_xor_sync(0xffffffffu, m, o));
        float e0 = expf(x0 - m);
        float e1 = (lane < 24) ? expf(x1 - m) : 0.f;
        float s = e0 + e1;
#pragma unroll
        for (int o = 16; o > 0; o >>= 1) s += __shfl_xor_sync(0xffffffffu, s, o);
        float inv = 1.0f / s;
        smx[i][lane] = e0 * inv;
        if (lane < 24) smx[i][lane + 32] = e1 * inv;
    }
    __syncwarp();
    {   // O = P V
        float acc[4][4];
#pragma unroll
        for (int nt = 0; nt < 4; nt++)
#pragma unroll
            for (int e = 0; e < 4; e++) acc[nt][e] = 0.f;
#pragma unroll
        for (int jt = 0; jt < 7; jt++) {
            int j8 = jt * 8;
            unsigned a0 = f2tf(smx[wr + gid][j8 + tig]);
            unsigned a1 = f2tf(smx[wr + gid + 8][j8 + tig]);
            unsigned a2 = f2tf(smx[wr + gid][j8 + tig + 4]);
            unsigned a3 = f2tf(smx[wr + gid + 8][j8 + tig + 4]);
#pragma unroll
            for (int nt = 0; nt < 4; nt++) {
                unsigned b0 = vs[j8 + tig][nt * 8 + gid];
                unsigned b1 = vs[j8 + tig + 4][nt * 8 + gid];
                mma8(acc[nt], a0, a1, a2, a3, b0, b1);
            }
        }
#pragma unroll
        for (int nt = 0; nt < 4; nt++)
#pragma unroll
            for (int h = 0; h < 2; h++) {
                int i = wr + gid + h * 8;
                int d = nt * 8 + tig * 2;
                if (i < 49)
                    *(__half2*)(g_oh + base + (size_t)i * 512 + d) =
                        __floats2half2_rn(acc[nt][h * 2], acc[nt][h * 2 + 1]);
            }
    }
}

// ---------------- launch ----------------------------------------------------
extern "C" void kernel_launch(void* const* d_in, const int* in_sizes, int n_in,
                              void* d_out, int out_size) {
    const float* x   = (const float*)d_in[0];
    const float* Wq  = (const float*)d_in[1];
    const float* bq  = (const float*)d_in[2];
    const float* Wk  = (const float*)d_in[3];
    const float* bk  = (const float*)d_in[4];
    const float* Wv  = (const float*)d_in[5];
    const float* bv  = (const float*)d_in[6];
    const float* Wp  = (const float*)d_in[7];
    const float* bp  = (const float*)d_in[8];
    const float* rb  = (const float*)d_in[9];
    const float* g1  = (const float*)d_in[10];
    const float* b1  = (const float*)d_in[11];
    const float* g2  = (const float*)d_in[12];
    const float* b2  = (const float*)d_in[13];
    const float* W1  = (const float*)d_in[14];
    const float* bf1 = (const float*)d_in[15];
    const float* W2  = (const float*)d_in[16];
    const float* bf2 = (const float*)d_in[17];
    float* out = (float*)d_out;

    cudaFuncSetAttribute(k_gemm_qkv,  cudaFuncAttributeMaxDynamicSharedMemorySize, SMEM_BYTES);
    cudaFuncSetAttribute(k_gemm_proj, cudaFuncAttributeMaxDynamicSharedMemorySize, SMEM_BYTES);
    cudaFuncSetAttribute(k_gemm_mlp1, cudaFuncAttributeMaxDynamicSharedMemorySize, SMEM_BYTES);
    cudaFuncSetAttribute(k_gemm_mlp2, cudaFuncAttributeMaxDynamicSharedMemorySize, SMEM_BYTES);

    // 0. batched pre-transpose + f16 convert (2 launches; ncu idx5 = proj)
    k_transpose4<<<dim3(16, 16, 4), 256>>>(Wq, Wk, Wv, Wp);
    k_transpose2<<<dim3(64, 64, 2), 256>>>(W1, W2);
    // 1. LN1 + window partition permute -> g_hh (f16, window order)
    ln_kernel<true><<<M_ROWS, 128>>>(x, g1, b1);
    // 2. Q/K/V projection (fp16 HMMA, 128x256 tiles, 3-stage)
    k_gemm_qkv<<<dim3(6, 392), 256, SMEM_BYTES>>>(bq, bk, bv);
    // 3. windowed attention -> g_oh
    k_attn<<<dim3(1024, 16), 128>>>(rb);
    // 4. output projection + window reverse + residual -> d_out (f32)  [ncu idx 5]
    k_gemm_proj<<<dim3(2, 392), 256, SMEM_BYTES>>>(bp, x, out);
    // 5. LN2 -> g_hh (f16, row order)
    ln_kernel<false><<<M_ROWS, 128>>>(out, g2, b2);
    // 6. MLP fc1 + exact GELU -> g_hid (f16)
    k_gemm_mlp1<<<dim3(8, 392), 256, SMEM_BYTES>>>(bf1);
    // 7. MLP fc2 + residual add into d_out
    k_gemm_mlp2<<<dim3(2, 392), 256, SMEM_BYTES>>>(bf2, out);
}